// round 1
// baseline (speedup 1.0000x reference)
#include <cuda_runtime.h>
#include <math.h>

// ---------------- problem constants ----------------
#define TOK    100352          // 32 * 56 * 56 tokens
#define CC     256
#define HEADS  8
#define HD     32
#define WS     7
#define NWIN   49              // tokens per window
#define MLPD   1024
#define HH     56
#define WW     56
#define SSH    3
#define NWB    64              // windows per batch image (8x8)
#define NWTOT  2048            // total windows (32*64)
#define ATT_SCALE 0.17677669529663687f   // 32^-0.5
#define LN_EPS 1e-5f

// ---------------- scratch (static device globals; no allocation) ----------------
__device__ float g_xw  [(size_t)TOK * CC];      // LN1 + shift + window partition
__device__ float g_qkv [(size_t)TOK * 3 * CC];  // QKV
__device__ float g_att [(size_t)TOK * CC];      // attention out (window layout)
__device__ float g_x1  [(size_t)TOK * CC];      // residual-1 result
__device__ float g_xn2 [(size_t)TOK * CC];      // LN2 out
__device__ float g_h   [(size_t)TOK * MLPD];    // MLP hidden

// ---------------- LN1 + roll(-3,-3) + window partition (gather) ----------------
__global__ void ln_shift_kernel(const float* __restrict__ x,
                                const float* __restrict__ g,
                                const float* __restrict__ b,
                                float* __restrict__ out)
{
    int t = blockIdx.x;                 // token in window layout
    int w = t / NWIN, n = t % NWIN;
    int bb = w / NWB, wi = w % NWB;
    int wy = wi >> 3, wx = wi & 7;
    int hy = wy * WS + n / WS, hx = wx * WS + n % WS;     // shifted-image coords
    int sy = (hy + SSH) % HH, sx = (hx + SSH) % WW;       // original coords
    const float* row = x + ((size_t)bb * HH * WW + sy * WW + sx) * CC;

    int c = threadIdx.x;
    float v = row[c];
    __shared__ float s1[256], s2[256];
    s1[c] = v; s2[c] = v * v;
    __syncthreads();
    #pragma unroll
    for (int st = 128; st > 0; st >>= 1) {
        if (c < st) { s1[c] += s1[c + st]; s2[c] += s2[c + st]; }
        __syncthreads();
    }
    float mu  = s1[0] * (1.0f / CC);
    float var = s2[0] * (1.0f / CC) - mu * mu;
    float inv = rsqrtf(var + LN_EPS);
    out[(size_t)t * CC + c] = (v - mu) * inv * g[c] + b[c];
}

// ---------------- plain LN (per token) ----------------
__global__ void ln_kernel(const float* __restrict__ x,
                          const float* __restrict__ g,
                          const float* __restrict__ b,
                          float* __restrict__ out)
{
    int t = blockIdx.x;
    const float* row = x + (size_t)t * CC;
    int c = threadIdx.x;
    float v = row[c];
    __shared__ float s1[256], s2[256];
    s1[c] = v; s2[c] = v * v;
    __syncthreads();
    #pragma unroll
    for (int st = 128; st > 0; st >>= 1) {
        if (c < st) { s1[c] += s1[c + st]; s2[c] += s2[c + st]; }
        __syncthreads();
    }
    float mu  = s1[0] * (1.0f / CC);
    float var = s2[0] * (1.0f / CC) - mu * mu;
    float inv = rsqrtf(var + LN_EPS);
    out[(size_t)t * CC + c] = (v - mu) * inv * g[c] + b[c];
}

// ---------------- generic fp32 tiled GEMM: C = A[M,K] @ B[K,N] + epilogue ----------------
// 64x64 tile, K-tile 16, 256 threads, 4x4 micro-tile. All dims divide exactly.
// MODE 0: out = acc + bias                       (QKV)
// MODE 1: window-reverse + roll(+3,+3) scatter, out = x_res + acc + bias   (proj)
// MODE 2: out = gelu_exact(acc + bias)           (MLP1)
// MODE 3: out = res + acc + bias                 (MLP2 -> d_out)
template<int MODE, int KDIM, int NDIM>
__global__ void gemm_kernel(const float* __restrict__ A,
                            const float* __restrict__ Bw,
                            const float* __restrict__ bias,
                            float* __restrict__ Out,
                            const float* __restrict__ res)
{
    const int m0 = blockIdx.y * 64;
    const int n0 = blockIdx.x * 64;
    __shared__ float As[16][64];
    __shared__ float Bs[16][68];

    const int tid = threadIdx.x;
    const int tx  = tid & 15;    // 16 col groups
    const int ty  = tid >> 4;    // 16 row groups

    float acc[4][4] = {};

    for (int k0 = 0; k0 < KDIM; k0 += 16) {
        {   // A tile: 64 rows x 16 K, one float4 per thread, store transposed
            int row = tid >> 2;           // 0..63
            int cg  = (tid & 3) * 4;      // 0,4,8,12
            float4 a = *reinterpret_cast<const float4*>(
                A + (size_t)(m0 + row) * KDIM + k0 + cg);
            As[cg + 0][row] = a.x; As[cg + 1][row] = a.y;
            As[cg + 2][row] = a.z; As[cg + 3][row] = a.w;
        }
        {   // B tile: 16 K-rows x 64 cols, one float4 per thread
            int row = tid >> 4;           // 0..15
            int cg  = (tid & 15) * 4;     // 0..60
            float4 bv = *reinterpret_cast<const float4*>(
                Bw + (size_t)(k0 + row) * NDIM + n0 + cg);
            *reinterpret_cast<float4*>(&Bs[row][cg]) = bv;
        }
        __syncthreads();
        #pragma unroll
        for (int kk = 0; kk < 16; kk++) {
            float a[4], bvv[4];
            #pragma unroll
            for (int i = 0; i < 4; i++) a[i]   = As[kk][ty * 4 + i];
            #pragma unroll
            for (int j = 0; j < 4; j++) bvv[j] = Bs[kk][tx * 4 + j];
            #pragma unroll
            for (int i = 0; i < 4; i++)
                #pragma unroll
                for (int j = 0; j < 4; j++)
                    acc[i][j] += a[i] * bvv[j];
        }
        __syncthreads();
    }

    // -------- epilogue --------
    #pragma unroll
    for (int i = 0; i < 4; i++) {
        int m = m0 + ty * 4 + i;
        size_t drow;
        if (MODE == 1) {
            int w = m / NWIN, ntok = m % NWIN;
            int bb = w / NWB, wi = w % NWB;
            int wy = wi >> 3, wx = wi & 7;
            int hy = wy * WS + ntok / WS, hx = wx * WS + ntok % WS;
            int oy = (hy + SSH) % HH, ox = (hx + SSH) % WW;
            drow = ((size_t)bb * HH * WW + oy * WW + ox) * CC;
        } else {
            drow = (size_t)m * NDIM;
        }
        #pragma unroll
        for (int j = 0; j < 4; j++) {
            int n = n0 + tx * 4 + j;
            float v = acc[i][j] + bias[n];
            if (MODE == 0) {
                Out[drow + n] = v;
            } else if (MODE == 1) {
                Out[drow + n] = res[drow + n] + v;
            } else if (MODE == 2) {
                Out[drow + n] = 0.5f * v * (1.0f + erff(v * 0.70710678118654752f));
            } else { // MODE 3
                Out[drow + n] = res[drow + n] + v;
            }
        }
    }
}

// ---------------- windowed attention: one block per (window, head) ----------------
__global__ void attn_kernel(const float* __restrict__ qkv,
                            const float* __restrict__ rel_bias,
                            float* __restrict__ out)
{
    int w    = blockIdx.x;   // 0..2047
    int head = blockIdx.y;   // 0..7
    int tid  = threadIdx.x;  // 256 threads

    __shared__ float q[NWIN][HD], k[NWIN][HD], v[NWIN][HD];
    __shared__ float s[NWIN][52];
    __shared__ float bias_s[169];

    for (int i = tid; i < 169; i += 256)
        bias_s[i] = rel_bias[i * HEADS + head];

    for (int idx = tid; idx < NWIN * HD; idx += 256) {
        int n = idx >> 5, d = idx & 31;
        size_t base = ((size_t)(w * NWIN + n)) * (3 * CC) + head * HD + d;
        q[n][d] = qkv[base];
        k[n][d] = qkv[base + CC];
        v[n][d] = qkv[base + 2 * CC];
    }
    __syncthreads();

    int wi = w % NWB;
    int wy = wi >> 3, wx = wi & 7;

    // scores + rel-pos bias + shift mask
    for (int idx = tid; idx < NWIN * NWIN; idx += 256) {
        int i = idx / NWIN, j = idx % NWIN;
        float dot = 0.0f;
        #pragma unroll
        for (int d = 0; d < HD; d++) dot += q[i][d] * k[j][d];
        int yi = i / WS, xi = i % WS, yj = j / WS, xj = j % WS;
        int rp = (yi - yj + WS - 1) * (2 * WS - 1) + (xi - xj + WS - 1);
        int gyi = wy * WS + yi, gxi = wx * WS + xi;
        int gyj = wy * WS + yj, gxj = wx * WS + xj;
        int ri = (gyi < HH - WS ? 0 : (gyi < HH - SSH ? 1 : 2)) * 3
               + (gxi < WW - WS ? 0 : (gxi < WW - SSH ? 1 : 2));
        int rj = (gyj < HH - WS ? 0 : (gyj < HH - SSH ? 1 : 2)) * 3
               + (gxj < WW - WS ? 0 : (gxj < WW - SSH ? 1 : 2));
        float mask = (ri != rj) ? -100.0f : 0.0f;
        s[i][j] = dot * ATT_SCALE + bias_s[rp] + mask;
    }
    __syncthreads();

    // softmax: one warp per row
    int warp = tid >> 5, lane = tid & 31;
    for (int i = warp; i < NWIN; i += 8) {
        float m = -1e30f;
        for (int j = lane; j < NWIN; j += 32) m = fmaxf(m, s[i][j]);
        #pragma unroll
        for (int o = 16; o > 0; o >>= 1) m = fmaxf(m, __shfl_xor_sync(0xffffffff, m, o));
        float sum = 0.0f;
        for (int j = lane; j < NWIN; j += 32) { float e = __expf(s[i][j] - m); s[i][j] = e; sum += e; }
        #pragma unroll
        for (int o = 16; o > 0; o >>= 1) sum += __shfl_xor_sync(0xffffffff, sum, o);
        float inv = 1.0f / sum;
        for (int j = lane; j < NWIN; j += 32) s[i][j] *= inv;
    }
    __syncthreads();

    // out = P @ V
    for (int idx = tid; idx < NWIN * HD; idx += 256) {
        int i = idx >> 5, d = idx & 31;
        float acc = 0.0f;
        #pragma unroll
        for (int j = 0; j < NWIN; j++) acc += s[i][j] * v[j][d];
        out[((size_t)(w * NWIN + i)) * CC + head * HD + d] = acc;
    }
}

// ---------------- launcher ----------------
extern "C" void kernel_launch(void* const* d_in, const int* in_sizes, int n_in,
                              void* d_out, int out_size)
{
    (void)in_sizes; (void)n_in; (void)out_size;
    const float* x        = (const float*)d_in[0];
    const float* qkv_w    = (const float*)d_in[1];
    const float* qkv_b    = (const float*)d_in[2];
    const float* proj_w   = (const float*)d_in[3];
    const float* proj_b   = (const float*)d_in[4];
    const float* rel_bias = (const float*)d_in[5];
    const float* ln1_g    = (const float*)d_in[6];
    const float* ln1_b    = (const float*)d_in[7];
    const float* ln2_g    = (const float*)d_in[8];
    const float* ln2_b    = (const float*)d_in[9];
    const float* mlp_w1   = (const float*)d_in[10];
    const float* mlp_b1   = (const float*)d_in[11];
    const float* mlp_w2   = (const float*)d_in[12];
    const float* mlp_b2   = (const float*)d_in[13];
    float* out = (float*)d_out;

    float *xw, *qkvb, *att, *x1, *xn2, *hbuf;
    cudaGetSymbolAddress((void**)&xw,   g_xw);
    cudaGetSymbolAddress((void**)&qkvb, g_qkv);
    cudaGetSymbolAddress((void**)&att,  g_att);
    cudaGetSymbolAddress((void**)&x1,   g_x1);
    cudaGetSymbolAddress((void**)&xn2,  g_xn2);
    cudaGetSymbolAddress((void**)&hbuf, g_h);

    // 1. LN1 + shift + window partition
    ln_shift_kernel<<<TOK, 256>>>(x, ln1_g, ln1_b, xw);
    // 2. QKV GEMM  [100352,256] @ [256,768]
    gemm_kernel<0, 256, 768><<<dim3(768 / 64, TOK / 64), 256>>>(xw, qkv_w, qkv_b, qkvb, nullptr);
    // 3. windowed attention
    attn_kernel<<<dim3(NWTOT, HEADS), 256>>>(qkvb, rel_bias, att);
    // 4. proj GEMM + window reverse + roll + residual
    gemm_kernel<1, 256, 256><<<dim3(256 / 64, TOK / 64), 256>>>(att, proj_w, proj_b, x1, x);
    // 5. LN2
    ln_kernel<<<TOK, 256>>>(x1, ln2_g, ln2_b, xn2);
    // 6. MLP1 + exact GELU
    gemm_kernel<2, 256, 1024><<<dim3(1024 / 64, TOK / 64), 256>>>(xn2, mlp_w1, mlp_b1, hbuf, nullptr);
    // 7. MLP2 + residual -> d_out
    gemm_kernel<3, 1024, 256><<<dim3(256 / 64, TOK / 64), 256>>>(hbuf, mlp_w2, mlp_b2, out, x1);
}

// round 3
// speedup vs baseline: 2.2934x; 2.2934x over previous
#include <cuda_runtime.h>
#include <math.h>
#include <cstdint>

// ---------------- problem constants ----------------
#define TOK    100352          // 32 * 56 * 56 tokens
#define CC     256
#define HEADS  8
#define HD     32
#define WS     7
#define NWIN   49
#define MLPD   1024
#define HH     56
#define WW     56
#define SSH    3
#define NWB    64
#define NWTOT  2048
#define ATT_SCALE 0.17677669529663687f
#define LN_EPS 1e-5f

// ---------------- scratch (static device globals; no allocation) ----------------
__device__ float g_xw  [(size_t)TOK * CC];
__device__ float g_qkv [(size_t)TOK * 3 * CC];
__device__ float g_att [(size_t)TOK * CC];
__device__ float g_x1  [(size_t)TOK * CC];
__device__ float g_xn2 [(size_t)TOK * CC];
__device__ float g_h   [(size_t)TOK * MLPD];
// transposed weights [N,K] row-major, tf32-rounded
__device__ float g_wq [768 * 256];
__device__ float g_wp [256 * 256];
__device__ float g_w1 [1024 * 256];
__device__ float g_w2 [256 * 1024];

// ---------------- helpers ----------------
__device__ __forceinline__ uint32_t smem_u32(const void* p) {
    uint32_t a;
    asm("{ .reg .u64 t; cvta.to.shared.u64 t, %1; cvt.u32.u64 %0, t; }" : "=r"(a) : "l"(p));
    return a;
}
__device__ __forceinline__ float f2tf32(float x) {
    uint32_t u;
    asm("cvt.rna.tf32.f32 %0, %1;" : "=r"(u) : "f"(x));
    return __uint_as_float(u);
}
__device__ __forceinline__ void cp_async16(uint32_t dst, const void* src) {
    asm volatile("cp.async.cg.shared.global [%0], [%1], 16;" :: "r"(dst), "l"(src));
}
#define CP_COMMIT() asm volatile("cp.async.commit_group;" ::: "memory")

// m16n8k8 tf32 MMA, fp32 accumulate
__device__ __forceinline__ void mma_tf32(float* c,
                                         uint32_t a0, uint32_t a1, uint32_t a2, uint32_t a3,
                                         uint32_t b0, uint32_t b1) {
    asm volatile(
        "mma.sync.aligned.m16n8k8.row.col.f32.tf32.tf32.f32 "
        "{%0,%1,%2,%3}, {%4,%5,%6,%7}, {%8,%9}, {%0,%1,%2,%3};"
        : "+f"(c[0]), "+f"(c[1]), "+f"(c[2]), "+f"(c[3])
        : "r"(a0), "r"(a1), "r"(a2), "r"(a3), "r"(b0), "r"(b1));
}

// ---------------- tensor-core GEMM: D[M,N] = A[M,K] @ Wt[N,K]^T + epilogue ----------------
// CTA 128x128, 8 warps of 64x32, K-chunk 32, double-buffered cp.async.
// A and Wt must already be tf32-rounded (producers handle it).
// MODE 0: +bias (QKV)   MODE 1: window-reverse scatter, res+acc+bias (proj)
// MODE 2: rna(gelu(acc+bias)) (MLP1)   MODE 3: res+acc+bias (MLP2)
#define LDK 36   // padded K stride (floats) per row in SMEM
template<int MODE, int KDIM, int NDIM>
__global__ __launch_bounds__(256)
void mma_gemm(const float* __restrict__ A, const float* __restrict__ Wt,
              const float* __restrict__ bias, float* __restrict__ Out,
              const float* __restrict__ res)
{
    extern __shared__ float sm[];   // 2 stages * (A 128*36 + B 128*36)
    const uint32_t sbase = smem_u32(sm);

    const int tid  = threadIdx.x;
    const int wid  = tid >> 5, lane = tid & 31;
    const int g    = lane >> 2, t4 = lane & 3;
    const int wm   = (wid & 1) * 64;     // warp m offset in tile
    const int wn   = (wid >> 1) * 32;    // warp n offset in tile
    const int m0   = blockIdx.y * 128;
    const int n0   = blockIdx.x * 128;

    constexpr int NC = KDIM / 32;
    constexpr int STAGE = 2 * 128 * LDK;          // floats per stage (A+B)

    auto load_chunk = [&](int c, int s) {
        const int k0 = c * 32;
        uint32_t sa = sbase + (uint32_t)(s * STAGE) * 4u;
        uint32_t sbuf = sa + 128u * LDK * 4u;
        #pragma unroll
        for (int t = 0; t < 4; t++) {
            int f = t * 256 + tid;          // 0..1023
            int row = f >> 3, cg = f & 7;
            cp_async16(sa   + (uint32_t)(row * LDK + cg * 4) * 4u,
                       A  + (size_t)(m0 + row) * KDIM + k0 + cg * 4);
            cp_async16(sbuf + (uint32_t)(row * LDK + cg * 4) * 4u,
                       Wt + (size_t)(n0 + row) * KDIM + k0 + cg * 4);
        }
        CP_COMMIT();
    };

    float acc[4][4][4];
    #pragma unroll
    for (int i = 0; i < 4; i++)
        #pragma unroll
        for (int j = 0; j < 4; j++)
            #pragma unroll
            for (int e = 0; e < 4; e++) acc[i][j][e] = 0.0f;

    load_chunk(0, 0);
    if (NC > 1) load_chunk(1, 1);

    for (int c = 0; c < NC; c++) {
        if (c + 1 < NC) asm volatile("cp.async.wait_group 1;" ::: "memory");
        else            asm volatile("cp.async.wait_group 0;" ::: "memory");
        __syncthreads();

        const float* As = sm + (c & 1) * STAGE;
        const float* Bs = As + 128 * LDK;
        #pragma unroll
        for (int kk = 0; kk < 4; kk++) {
            const int kb = kk * 8;
            uint32_t bf[4][2];
            #pragma unroll
            for (int ni = 0; ni < 4; ni++) {
                const float* bp = Bs + (wn + ni * 8 + g) * LDK + kb + t4;
                bf[ni][0] = __float_as_uint(bp[0]);
                bf[ni][1] = __float_as_uint(bp[4]);
            }
            #pragma unroll
            for (int mi = 0; mi < 4; mi++) {
                const float* ap = As + (wm + mi * 16 + g) * LDK + kb + t4;
                uint32_t a0 = __float_as_uint(ap[0]);
                uint32_t a1 = __float_as_uint(ap[8 * LDK]);
                uint32_t a2 = __float_as_uint(ap[4]);
                uint32_t a3 = __float_as_uint(ap[8 * LDK + 4]);
                #pragma unroll
                for (int ni = 0; ni < 4; ni++)
                    mma_tf32(acc[mi][ni], a0, a1, a2, a3, bf[ni][0], bf[ni][1]);
            }
        }
        if (c + 2 < NC) {
            __syncthreads();
            load_chunk(c + 2, c & 1);
        }
    }

    // -------- epilogue --------
    #pragma unroll
    for (int mi = 0; mi < 4; mi++) {
        #pragma unroll
        for (int h = 0; h < 2; h++) {
            int m = m0 + wm + mi * 16 + g + h * 8;
            size_t drow;
            if (MODE == 1) {
                int w = m / NWIN, ntok = m % NWIN;
                int bb2 = w / NWB, wi = w % NWB;
                int wy = wi >> 3, wx = wi & 7;
                int hy = wy * WS + ntok / WS, hx = wx * WS + ntok % WS;
                int oy = (hy + SSH) % HH, ox = (hx + SSH) % WW;
                drow = ((size_t)bb2 * HH * WW + oy * WW + ox) * CC;
            } else {
                drow = (size_t)m * NDIM;
            }
            #pragma unroll
            for (int ni = 0; ni < 4; ni++) {
                int n = n0 + wn + ni * 8 + 2 * t4;
                float2 bv = *reinterpret_cast<const float2*>(bias + n);
                float vx = acc[mi][ni][2 * h + 0] + bv.x;
                float vy = acc[mi][ni][2 * h + 1] + bv.y;
                if (MODE == 1 || MODE == 3) {
                    float2 r = *reinterpret_cast<const float2*>(res + drow + n);
                    vx += r.x; vy += r.y;
                }
                if (MODE == 2) {
                    vx = f2tf32(0.5f * vx * (1.0f + erff(vx * 0.70710678118654752f)));
                    vy = f2tf32(0.5f * vy * (1.0f + erff(vy * 0.70710678118654752f)));
                }
                float2 o = { vx, vy };
                *reinterpret_cast<float2*>(Out + drow + n) = o;
            }
        }
    }
}

// ---------------- weight transpose + tf32 round: W[K,N] -> Wt[N,K] ----------------
__global__ void transpose_kernel(const float* __restrict__ W, float* __restrict__ Wt, int K, int N)
{
    __shared__ float t[32][33];
    int k0 = blockIdx.y * 32, n0 = blockIdx.x * 32;
    int tx = threadIdx.x, ty = threadIdx.y;   // 32 x 8
    for (int i = ty; i < 32; i += 8) t[i][tx] = W[(size_t)(k0 + i) * N + n0 + tx];
    __syncthreads();
    for (int i = ty; i < 32; i += 8) Wt[(size_t)(n0 + i) * K + k0 + tx] = f2tf32(t[tx][i]);
}

// ---------------- LN (warp per token), optional shift-gather, tf32-rounded output ----------------
template<bool SHIFT>
__global__ __launch_bounds__(256)
void ln_warp_kernel(const float* __restrict__ x,
                    const float* __restrict__ g,
                    const float* __restrict__ b,
                    float* __restrict__ out)
{
    int t = blockIdx.x * 8 + (threadIdx.x >> 5);
    int lane = threadIdx.x & 31;

    const float* row;
    if (SHIFT) {
        int w = t / NWIN, n = t % NWIN;
        int bb = w / NWB, wi = w % NWB;
        int wy = wi >> 3, wx = wi & 7;
        int hy = wy * WS + n / WS, hx = wx * WS + n % WS;
        int sy = (hy + SSH) % HH, sx = (hx + SSH) % WW;
        row = x + ((size_t)bb * HH * WW + sy * WW + sx) * CC;
    } else {
        row = x + (size_t)t * CC;
    }

    const float4* rp = reinterpret_cast<const float4*>(row);
    float4 a = rp[lane], c = rp[lane + 32];
    float s  = a.x + a.y + a.z + a.w + c.x + c.y + c.z + c.w;
    float s2 = a.x * a.x + a.y * a.y + a.z * a.z + a.w * a.w
             + c.x * c.x + c.y * c.y + c.z * c.z + c.w * c.w;
    #pragma unroll
    for (int o = 16; o > 0; o >>= 1) {
        s  += __shfl_xor_sync(0xffffffff, s, o);
        s2 += __shfl_xor_sync(0xffffffff, s2, o);
    }
    float mu  = s * (1.0f / CC);
    float var = s2 * (1.0f / CC) - mu * mu;
    float inv = rsqrtf(var + LN_EPS);

    const float4* gp = reinterpret_cast<const float4*>(g);
    const float4* bp = reinterpret_cast<const float4*>(b);
    float4* op = reinterpret_cast<float4*>(out + (size_t)t * CC);
    #pragma unroll
    for (int h = 0; h < 2; h++) {
        float4 v = h ? c : a;
        float4 gg = gp[lane + h * 32], bb4 = bp[lane + h * 32];
        float4 o;
        o.x = f2tf32((v.x - mu) * inv * gg.x + bb4.x);
        o.y = f2tf32((v.y - mu) * inv * gg.y + bb4.y);
        o.z = f2tf32((v.z - mu) * inv * gg.z + bb4.z);
        o.w = f2tf32((v.w - mu) * inv * gg.w + bb4.w);
        op[lane + h * 32] = o;
    }
}

// ---------------- windowed attention (tf32-rounded output) ----------------
__global__ void attn_kernel(const float* __restrict__ qkv,
                            const float* __restrict__ rel_bias,
                            float* __restrict__ out)
{
    int w    = blockIdx.x;
    int head = blockIdx.y;
    int tid  = threadIdx.x;

    __shared__ float q[NWIN][HD], k[NWIN][HD], v[NWIN][HD];
    __shared__ float s[NWIN][52];
    __shared__ float bias_s[169];

    for (int i = tid; i < 169; i += 256)
        bias_s[i] = rel_bias[i * HEADS + head];

    for (int idx = tid; idx < NWIN * HD; idx += 256) {
        int n = idx >> 5, d = idx & 31;
        size_t base = ((size_t)(w * NWIN + n)) * (3 * CC) + head * HD + d;
        q[n][d] = qkv[base];
        k[n][d] = qkv[base + CC];
        v[n][d] = qkv[base + 2 * CC];
    }
    __syncthreads();

    int wi = w % NWB;
    int wy = wi >> 3, wx = wi & 7;

    for (int idx = tid; idx < NWIN * NWIN; idx += 256) {
        int i = idx / NWIN, j = idx % NWIN;
        float dot = 0.0f;
        #pragma unroll
        for (int d = 0; d < HD; d++) dot += q[i][d] * k[j][d];
        int yi = i / WS, xi = i % WS, yj = j / WS, xj = j % WS;
        int rp = (yi - yj + WS - 1) * (2 * WS - 1) + (xi - xj + WS - 1);
        int gyi = wy * WS + yi, gxi = wx * WS + xi;
        int gyj = wy * WS + yj, gxj = wx * WS + xj;
        int ri = (gyi < HH - WS ? 0 : (gyi < HH - SSH ? 1 : 2)) * 3
               + (gxi < WW - WS ? 0 : (gxi < WW - SSH ? 1 : 2));
        int rj = (gyj < HH - WS ? 0 : (gyj < HH - SSH ? 1 : 2)) * 3
               + (gxj < WW - WS ? 0 : (gxj < WW - SSH ? 1 : 2));
        float mask = (ri != rj) ? -100.0f : 0.0f;
        s[i][j] = dot * ATT_SCALE + bias_s[rp] + mask;
    }
    __syncthreads();

    int warp = tid >> 5, lane = tid & 31;
    for (int i = warp; i < NWIN; i += 8) {
        float m = -1e30f;
        for (int j = lane; j < NWIN; j += 32) m = fmaxf(m, s[i][j]);
        #pragma unroll
        for (int o = 16; o > 0; o >>= 1) m = fmaxf(m, __shfl_xor_sync(0xffffffff, m, o));
        float sum = 0.0f;
        for (int j = lane; j < NWIN; j += 32) { float e = __expf(s[i][j] - m); s[i][j] = e; sum += e; }
        #pragma unroll
        for (int o = 16; o > 0; o >>= 1) sum += __shfl_xor_sync(0xffffffff, sum, o);
        float inv = 1.0f / sum;
        for (int j = lane; j < NWIN; j += 32) s[i][j] *= inv;
    }
    __syncthreads();

    for (int idx = tid; idx < NWIN * HD; idx += 256) {
        int i = idx >> 5, d = idx & 31;
        float acc = 0.0f;
        #pragma unroll
        for (int j = 0; j < NWIN; j++) acc += s[i][j] * v[j][d];
        out[((size_t)(w * NWIN + i)) * CC + head * HD + d] = f2tf32(acc);
    }
}

// ---------------- launcher ----------------
extern "C" void kernel_launch(void* const* d_in, const int* in_sizes, int n_in,
                              void* d_out, int out_size)
{
    (void)in_sizes; (void)n_in; (void)out_size;
    const float* x        = (const float*)d_in[0];
    const float* qkv_w    = (const float*)d_in[1];
    const float* qkv_b    = (const float*)d_in[2];
    const float* proj_w   = (const float*)d_in[3];
    const float* proj_b   = (const float*)d_in[4];
    const float* rel_bias = (const float*)d_in[5];
    const float* ln1_g    = (const float*)d_in[6];
    const float* ln1_b    = (const float*)d_in[7];
    const float* ln2_g    = (const float*)d_in[8];
    const float* ln2_b    = (const float*)d_in[9];
    const float* mlp_w1   = (const float*)d_in[10];
    const float* mlp_b1   = (const float*)d_in[11];
    const float* mlp_w2   = (const float*)d_in[12];
    const float* mlp_b2   = (const float*)d_in[13];
    float* out = (float*)d_out;

    float *xw, *qkvb, *att, *x1, *xn2, *hbuf, *wq, *wp, *w1, *w2;
    cudaGetSymbolAddress((void**)&xw,   g_xw);
    cudaGetSymbolAddress((void**)&qkvb, g_qkv);
    cudaGetSymbolAddress((void**)&att,  g_att);
    cudaGetSymbolAddress((void**)&x1,   g_x1);
    cudaGetSymbolAddress((void**)&xn2,  g_xn2);
    cudaGetSymbolAddress((void**)&hbuf, g_h);
    cudaGetSymbolAddress((void**)&wq,   g_wq);
    cudaGetSymbolAddress((void**)&wp,   g_wp);
    cudaGetSymbolAddress((void**)&w1,   g_w1);
    cudaGetSymbolAddress((void**)&w2,   g_w2);

    const int SMEM = 2 * 2 * 128 * LDK * 4;   // 73728 bytes
    cudaFuncSetAttribute(mma_gemm<0, 256,  768>, cudaFuncAttributeMaxDynamicSharedMemorySize, SMEM);
    cudaFuncSetAttribute(mma_gemm<1, 256,  256>, cudaFuncAttributeMaxDynamicSharedMemorySize, SMEM);
    cudaFuncSetAttribute(mma_gemm<2, 256, 1024>, cudaFuncAttributeMaxDynamicSharedMemorySize, SMEM);
    cudaFuncSetAttribute(mma_gemm<3, 1024, 256>, cudaFuncAttributeMaxDynamicSharedMemorySize, SMEM);

    // weight transposes + tf32 rounding (tiny)
    transpose_kernel<<<dim3(768 / 32, 256 / 32),  dim3(32, 8)>>>(qkv_w,  wq, 256, 768);
    transpose_kernel<<<dim3(256 / 32, 256 / 32),  dim3(32, 8)>>>(proj_w, wp, 256, 256);
    transpose_kernel<<<dim3(1024 / 32, 256 / 32), dim3(32, 8)>>>(mlp_w1, w1, 256, 1024);
    transpose_kernel<<<dim3(256 / 32, 1024 / 32), dim3(32, 8)>>>(mlp_w2, w2, 1024, 256);

    // 1. LN1 + shift + window partition (tf32-rounded)
    ln_warp_kernel<true><<<TOK / 8, 256>>>(x, ln1_g, ln1_b, xw);
    // 2. QKV GEMM
    mma_gemm<0, 256, 768><<<dim3(768 / 128, TOK / 128), 256, SMEM>>>(xw, wq, qkv_b, qkvb, nullptr);
    // 3. windowed attention (tf32-rounded out)
    attn_kernel<<<dim3(NWTOT, HEADS), 256>>>(qkvb, rel_bias, att);
    // 4. proj GEMM + window reverse + roll + residual
    mma_gemm<1, 256, 256><<<dim3(256 / 128, TOK / 128), 256, SMEM>>>(att, wp, proj_b, x1, x);
    // 5. LN2 (tf32-rounded)
    ln_warp_kernel<false><<<TOK / 8, 256>>>(x1, ln2_g, ln2_b, xn2);
    // 6. MLP1 + GELU (tf32-rounded)
    mma_gemm<2, 256, 1024><<<dim3(1024 / 128, TOK / 128), 256, SMEM>>>(xn2, w1, mlp_b1, hbuf, nullptr);
    // 7. MLP2 + residual -> d_out
    mma_gemm<3, 1024, 256><<<dim3(256 / 128, TOK / 128), 256, SMEM>>>(hbuf, w2, mlp_b2, out, x1);
}

// round 5
// speedup vs baseline: 3.0634x; 1.3358x over previous
#include <cuda_runtime.h>
#include <math.h>
#include <cstdint>

// ---------------- problem constants ----------------
#define TOK    100352          // 32 * 56 * 56 tokens
#define CC     256
#define HEADS  8
#define HD     32
#define WS     7
#define NWIN   49
#define MLPD   1024
#define HH     56
#define WW     56
#define SSH    3
#define NWB    64
#define NWTOT  2048
#define ATT_SCALE 0.17677669529663687f
#define LN_EPS 1e-5f

// ---------------- scratch (static device globals; no allocation) ----------------
__device__ float g_qkv [(size_t)TOK * 3 * CC];
__device__ float g_att [(size_t)TOK * CC];
__device__ float g_x1  [(size_t)TOK * CC];
__device__ float g_h   [(size_t)TOK * MLPD];
__device__ float2 g_st1[TOK];   // LN1 stats {mu, rsig} of x
__device__ float2 g_st2[TOK];   // LN2 stats of x1
// transposed weights [N,K] row-major, tf32-rounded
__device__ float g_wq [768 * 256];
__device__ float g_wp [256 * 256];
__device__ float g_w1 [1024 * 256];
__device__ float g_w2 [256 * 1024];

// ---------------- helpers ----------------
__device__ __forceinline__ uint32_t smem_u32(const void* p) {
    uint32_t a;
    asm("{ .reg .u64 t; cvta.to.shared.u64 t, %1; cvt.u32.u64 %0, t; }" : "=r"(a) : "l"(p));
    return a;
}
__device__ __forceinline__ float f2tf32(float x) {
    uint32_t u;
    asm("cvt.rna.tf32.f32 %0, %1;" : "=r"(u) : "f"(x));
    return __uint_as_float(u);
}
__device__ __forceinline__ void cp_async16(uint32_t dst, const void* src) {
    asm volatile("cp.async.cg.shared.global [%0], [%1], 16;" :: "r"(dst), "l"(src));
}
#define CP_COMMIT() asm volatile("cp.async.commit_group;" ::: "memory")

// m16n8k8 tf32 MMA, fp32 accumulate
__device__ __forceinline__ void mma_tf32(float* c,
                                         uint32_t a0, uint32_t a1, uint32_t a2, uint32_t a3,
                                         uint32_t b0, uint32_t b1) {
    asm volatile(
        "mma.sync.aligned.m16n8k8.row.col.f32.tf32.tf32.f32 "
        "{%0,%1,%2,%3}, {%4,%5,%6,%7}, {%8,%9}, {%0,%1,%2,%3};"
        : "+f"(c[0]), "+f"(c[1]), "+f"(c[2]), "+f"(c[3])
        : "r"(a0), "r"(a1), "r"(a2), "r"(a3), "r"(b0), "r"(b1));
}

#define LDK 36   // padded K stride (floats) per SMEM row

// shared MMA compute over one 32-K chunk
__device__ __forceinline__ void chunk_mma(const float* As, const float* Bs,
                                          int wm, int wn, int g, int t4,
                                          float acc[4][4][4]) {
    #pragma unroll
    for (int kk = 0; kk < 4; kk++) {
        const int kb = kk * 8;
        uint32_t bf[4][2];
        #pragma unroll
        for (int ni = 0; ni < 4; ni++) {
            const float* bp = Bs + (wn + ni * 8 + g) * LDK + kb + t4;
            bf[ni][0] = __float_as_uint(bp[0]);
            bf[ni][1] = __float_as_uint(bp[4]);
        }
        #pragma unroll
        for (int mi = 0; mi < 4; mi++) {
            const float* ap = As + (wm + mi * 16 + g) * LDK + kb + t4;
            uint32_t a0 = __float_as_uint(ap[0]);
            uint32_t a1 = __float_as_uint(ap[8 * LDK]);
            uint32_t a2 = __float_as_uint(ap[4]);
            uint32_t a3 = __float_as_uint(ap[8 * LDK + 4]);
            #pragma unroll
            for (int ni = 0; ni < 4; ni++)
                mma_tf32(acc[mi][ni], a0, a1, a2, a3, bf[ni][0], bf[ni][1]);
        }
    }
}

// shared epilogue
template<int MODE, int NDIM>
__device__ __forceinline__ void gemm_epilogue(float acc[4][4][4],
                                              int m0, int n0, int wm, int wn, int g, int t4,
                                              const float* __restrict__ bias,
                                              float* __restrict__ Out,
                                              const float* __restrict__ res) {
    #pragma unroll
    for (int mi = 0; mi < 4; mi++) {
        #pragma unroll
        for (int h = 0; h < 2; h++) {
            int m = m0 + wm + mi * 16 + g + h * 8;
            size_t drow;
            if (MODE == 1) {
                int w = m / NWIN, ntok = m % NWIN;
                int bb2 = w / NWB, wi = w % NWB;
                int wy = wi >> 3, wx = wi & 7;
                int hy = wy * WS + ntok / WS, hx = wx * WS + ntok % WS;
                int oy = (hy + SSH) % HH, ox = (hx + SSH) % WW;
                drow = ((size_t)bb2 * HH * WW + oy * WW + ox) * CC;
            } else {
                drow = (size_t)m * NDIM;
            }
            #pragma unroll
            for (int ni = 0; ni < 4; ni++) {
                int n = n0 + wn + ni * 8 + 2 * t4;
                float2 bv = *reinterpret_cast<const float2*>(bias + n);
                float vx = acc[mi][ni][2 * h + 0] + bv.x;
                float vy = acc[mi][ni][2 * h + 1] + bv.y;
                if (MODE == 1 || MODE == 3) {
                    float2 r = *reinterpret_cast<const float2*>(res + drow + n);
                    vx += r.x; vy += r.y;
                }
                if (MODE == 2) {
                    vx = f2tf32(0.5f * vx * (1.0f + erff(vx * 0.70710678118654752f)));
                    vy = f2tf32(0.5f * vy * (1.0f + erff(vy * 0.70710678118654752f)));
                }
                float2 o = { vx, vy };
                *reinterpret_cast<float2*>(Out + drow + n) = o;
            }
        }
    }
}

// ---------------- cp.async GEMM (A already tf32 in global): proj / MLP2 ----------------
template<int MODE, int KDIM, int NDIM>
__global__ __launch_bounds__(256)
void mma_gemm(const float* __restrict__ A, const float* __restrict__ Wt,
              const float* __restrict__ bias, float* __restrict__ Out,
              const float* __restrict__ res)
{
    extern __shared__ float sm[];
    const uint32_t sbase = smem_u32(sm);

    const int tid  = threadIdx.x;
    const int wid  = tid >> 5, lane = tid & 31;
    const int g    = lane >> 2, t4 = lane & 3;
    const int wm   = (wid & 1) * 64;
    const int wn   = (wid >> 1) * 32;
    const int m0   = blockIdx.y * 128;
    const int n0   = blockIdx.x * 128;

    constexpr int NC = KDIM / 32;
    constexpr int STAGE = 2 * 128 * LDK;

    auto load_chunk = [&](int c, int s) {
        const int k0 = c * 32;
        uint32_t sa = sbase + (uint32_t)(s * STAGE) * 4u;
        uint32_t sbuf = sa + 128u * LDK * 4u;
        #pragma unroll
        for (int t = 0; t < 4; t++) {
            int f = t * 256 + tid;
            int row = f >> 3, cg = f & 7;
            cp_async16(sa   + (uint32_t)(row * LDK + cg * 4) * 4u,
                       A  + (size_t)(m0 + row) * KDIM + k0 + cg * 4);
            cp_async16(sbuf + (uint32_t)(row * LDK + cg * 4) * 4u,
                       Wt + (size_t)(n0 + row) * KDIM + k0 + cg * 4);
        }
        CP_COMMIT();
    };

    float acc[4][4][4];
    #pragma unroll
    for (int i = 0; i < 4; i++)
        #pragma unroll
        for (int j = 0; j < 4; j++)
            #pragma unroll
            for (int e = 0; e < 4; e++) acc[i][j][e] = 0.0f;

    load_chunk(0, 0);
    if (NC > 1) load_chunk(1, 1);

    for (int c = 0; c < NC; c++) {
        if (c + 1 < NC) asm volatile("cp.async.wait_group 1;" ::: "memory");
        else            asm volatile("cp.async.wait_group 0;" ::: "memory");
        __syncthreads();
        const float* As = sm + (c & 1) * STAGE;
        const float* Bs = As + 128 * LDK;
        chunk_mma(As, Bs, wm, wn, g, t4, acc);
        if (c + 2 < NC) {
            __syncthreads();
            load_chunk(c + 2, c & 1);
        }
    }
    gemm_epilogue<MODE, NDIM>(acc, m0, n0, wm, wn, g, t4, bias, Out, res);
}

// ---------------- LN-fused GEMM (LDG -> normalize -> tf32 -> STS): QKV / MLP1 ----------------
// LNMODE 1: shift-gather LN from x (QKV)    LNMODE 2: plain LN (MLP1)
template<int MODE, int LNMODE, int KDIM, int NDIM>
__global__ __launch_bounds__(256)
void mma_gemm_ln(const float* __restrict__ X, const float* __restrict__ Wt,
                 const float2* __restrict__ stats,
                 const float* __restrict__ lng, const float* __restrict__ lnb,
                 const float* __restrict__ bias, float* __restrict__ Out)
{
    extern __shared__ float sm[];
    constexpr int STAGE = 2 * 128 * LDK;
    float* gS = sm + 2 * STAGE;          // 256 floats
    float* bS = gS + KDIM;               // 256 floats

    const int tid  = threadIdx.x;
    const int wid  = tid >> 5, lane = tid & 31;
    const int g    = lane >> 2, t4 = lane & 3;
    const int wm   = (wid & 1) * 64;
    const int wn   = (wid >> 1) * 32;
    const int m0   = blockIdx.y * 128;
    const int n0   = blockIdx.x * 128;

    constexpr int NC = KDIM / 32;

    if (tid < KDIM) { gS[tid] = lng[tid]; bS[tid] = lnb[tid]; }

    // per-thread fixed (row, cg) slots, 4 each for A and B
    int rowA[4], srcA[4];
    float2 stA[4];
    #pragma unroll
    for (int t = 0; t < 4; t++) {
        int f = t * 256 + tid;
        int row = f >> 3;
        rowA[t] = row;
        int m = m0 + row;
        int src;
        if (LNMODE == 1) {
            int w = m / NWIN, n = m % NWIN;
            int bb = w >> 6, wi = w & 63;
            int wy = wi >> 3, wx = wi & 7;
            int hy = wy * WS + n / WS, hx = wx * WS + n % WS;
            int sy = hy + SSH; if (sy >= HH) sy -= HH;
            int sx = hx + SSH; if (sx >= WW) sx -= WW;
            src = bb * (HH * WW) + sy * WW + sx;
        } else {
            src = m;
        }
        srcA[t] = src;
        stA[t] = __ldg(&stats[src]);
    }
    const int cg = tid & 7;

    float4 ra[4], rb[4];
    auto ldg_chunk = [&](int c) {
        const int k0 = c * 32;
        #pragma unroll
        for (int t = 0; t < 4; t++) {
            ra[t] = *reinterpret_cast<const float4*>(X + (size_t)srcA[t] * KDIM + k0 + cg * 4);
            rb[t] = *reinterpret_cast<const float4*>(Wt + (size_t)(n0 + rowA[t]) * KDIM + k0 + cg * 4);
        }
    };
    auto sts_chunk = [&](int c, int s) {
        const int k0 = c * 32;
        float* As = sm + s * STAGE;
        float* Bs = As + 128 * LDK;
        const float4 g4 = *reinterpret_cast<const float4*>(gS + k0 + cg * 4);
        const float4 b4 = *reinterpret_cast<const float4*>(bS + k0 + cg * 4);
        #pragma unroll
        for (int t = 0; t < 4; t++) {
            float mu = stA[t].x, inv = stA[t].y;
            float4 v = ra[t];
            float4 o;
            o.x = f2tf32((v.x - mu) * inv * g4.x + b4.x);
            o.y = f2tf32((v.y - mu) * inv * g4.y + b4.y);
            o.z = f2tf32((v.z - mu) * inv * g4.z + b4.z);
            o.w = f2tf32((v.w - mu) * inv * g4.w + b4.w);
            *reinterpret_cast<float4*>(As + rowA[t] * LDK + cg * 4) = o;
            *reinterpret_cast<float4*>(Bs + rowA[t] * LDK + cg * 4) = rb[t];
        }
    };

    float acc[4][4][4];
    #pragma unroll
    for (int i = 0; i < 4; i++)
        #pragma unroll
        for (int j = 0; j < 4; j++)
            #pragma unroll
            for (int e = 0; e < 4; e++) acc[i][j][e] = 0.0f;

    ldg_chunk(0);
    __syncthreads();        // *** gS/bS visible to all threads before first sts_chunk ***
    sts_chunk(0, 0);
    if (NC > 1) ldg_chunk(1);
    __syncthreads();        // stage 0 fully written

    for (int c = 0; c < NC; c++) {
        int s = c & 1;
        chunk_mma(sm + s * STAGE, sm + s * STAGE + 128 * LDK, wm, wn, g, t4, acc);
        if (c + 1 < NC) {
            __syncthreads();                // all warps done reading stage s^1 (used at c-1)
            sts_chunk(c + 1, s ^ 1);
            if (c + 2 < NC) ldg_chunk(c + 2);
            __syncthreads();                // stage s^1 now holds chunk c+1
        }
    }
    gemm_epilogue<MODE, NDIM>(acc, m0, n0, wm, wn, g, t4, bias, Out, nullptr);
}

// ---------------- LN stats: warp per token -> {mu, rsig} ----------------
__global__ __launch_bounds__(256)
void ln_stats_kernel(const float* __restrict__ x, float2* __restrict__ st)
{
    int t = blockIdx.x * 8 + (threadIdx.x >> 5);
    int lane = threadIdx.x & 31;
    const float4* rp = reinterpret_cast<const float4*>(x + (size_t)t * CC);
    float4 a = rp[lane], c = rp[lane + 32];
    float s  = a.x + a.y + a.z + a.w + c.x + c.y + c.z + c.w;
    float s2 = a.x * a.x + a.y * a.y + a.z * a.z + a.w * a.w
             + c.x * c.x + c.y * c.y + c.z * c.z + c.w * c.w;
    #pragma unroll
    for (int o = 16; o > 0; o >>= 1) {
        s  += __shfl_xor_sync(0xffffffff, s, o);
        s2 += __shfl_xor_sync(0xffffffff, s2, o);
    }
    if (lane == 0) {
        float mu  = s * (1.0f / CC);
        float var = s2 * (1.0f / CC) - mu * mu;
        st[t] = make_float2(mu, rsqrtf(var + LN_EPS));
    }
}

// ---------------- weight transpose + tf32 round: W[K,N] -> Wt[N,K] ----------------
__global__ void transpose_kernel(const float* __restrict__ W, float* __restrict__ Wt, int K, int N)
{
    __shared__ float t[32][33];
    int k0 = blockIdx.y * 32, n0 = blockIdx.x * 32;
    int tx = threadIdx.x, ty = threadIdx.y;
    for (int i = ty; i < 32; i += 8) t[i][tx] = W[(size_t)(k0 + i) * N + n0 + tx];
    __syncthreads();
    for (int i = ty; i < 32; i += 8) Wt[(size_t)(n0 + i) * K + k0 + tx] = f2tf32(t[tx][i]);
}

// ---------------- windowed attention (padded SMEM, tf32-rounded output) ----------------
__global__ __launch_bounds__(256)
void attn_kernel(const float* __restrict__ qkv,
                 const float* __restrict__ rel_bias,
                 float* __restrict__ out)
{
    int w    = blockIdx.x;
    int head = blockIdx.y;
    int tid  = threadIdx.x;

    __shared__ float q[NWIN][HD];          // broadcast reads -> no pad needed
    __shared__ float k[NWIN][HD + 1];      // pad 33: conflict-free k[j][d] with lanes on j
    __shared__ float v[NWIN][HD + 1];
    __shared__ float s[NWIN][52];
    __shared__ float bias_s[169];

    for (int i = tid; i < 169; i += 256)
        bias_s[i] = rel_bias[i * HEADS + head];

    for (int idx = tid; idx < NWIN * HD; idx += 256) {
        int n = idx >> 5, d = idx & 31;
        size_t base = ((size_t)(w * NWIN + n)) * (3 * CC) + head * HD + d;
        q[n][d] = qkv[base];
        k[n][d] = qkv[base + CC];
        v[n][d] = qkv[base + 2 * CC];
    }
    __syncthreads();

    int wi = w % NWB;
    int wy = wi >> 3, wx = wi & 7;

    for (int idx = tid; idx < NWIN * NWIN; idx += 256) {
        int i = idx / NWIN, j = idx % NWIN;
        float dot = 0.0f;
        #pragma unroll
        for (int d = 0; d < HD; d++) dot += q[i][d] * k[j][d];
        int yi = i / WS, xi = i % WS, yj = j / WS, xj = j % WS;
        int rp = (yi - yj + WS - 1) * (2 * WS - 1) + (xi - xj + WS - 1);
        int gyi = wy * WS + yi, gxi = wx * WS + xi;
        int gyj = wy * WS + yj, gxj = wx * WS + xj;
        int ri = (gyi < HH - WS ? 0 : (gyi < HH - SSH ? 1 : 2)) * 3
               + (gxi < WW - WS ? 0 : (gxi < WW - SSH ? 1 : 2));
        int rj = (gyj < HH - WS ? 0 : (gyj < HH - SSH ? 1 : 2)) * 3
               + (gxj < WW - WS ? 0 : (gxj < WW - SSH ? 1 : 2));
        float mask = (ri != rj) ? -100.0f : 0.0f;
        s[i][j] = dot * ATT_SCALE + bias_s[rp] + mask;
    }
    __syncthreads();

    int warp = tid >> 5, lane = tid & 31;
    for (int i = warp; i < NWIN; i += 8) {
        float m = -1e30f;
        for (int j = lane; j < NWIN; j += 32) m = fmaxf(m, s[i][j]);
        #pragma unroll
        for (int o = 16; o > 0; o >>= 1) m = fmaxf(m, __shfl_xor_sync(0xffffffff, m, o));
        float sum = 0.0f;
        for (int j = lane; j < NWIN; j += 32) { float e = __expf(s[i][j] - m); s[i][j] = e; sum += e; }
        #pragma unroll
        for (int o = 16; o > 0; o >>= 1) sum += __shfl_xor_sync(0xffffffff, sum, o);
        float inv = 1.0f / sum;
        for (int j = lane; j < NWIN; j += 32) s[i][j] *= inv;
    }
    __syncthreads();

    for (int idx = tid; idx < NWIN * HD; idx += 256) {
        int i = idx >> 5, d = idx & 31;
        float acc = 0.0f;
        #pragma unroll
        for (int j = 0; j < NWIN; j++) acc += s[i][j] * v[j][d];
        out[((size_t)(w * NWIN + i)) * CC + head * HD + d] = f2tf32(acc);
    }
}

// ---------------- launcher ----------------
extern "C" void kernel_launch(void* const* d_in, const int* in_sizes, int n_in,
                              void* d_out, int out_size)
{
    (void)in_sizes; (void)n_in; (void)out_size;
    const float* x        = (const float*)d_in[0];
    const float* qkv_w    = (const float*)d_in[1];
    const float* qkv_b    = (const float*)d_in[2];
    const float* proj_w   = (const float*)d_in[3];
    const float* proj_b   = (const float*)d_in[4];
    const float* rel_bias = (const float*)d_in[5];
    const float* ln1_g    = (const float*)d_in[6];
    const float* ln1_b    = (const float*)d_in[7];
    const float* ln2_g    = (const float*)d_in[8];
    const float* ln2_b    = (const float*)d_in[9];
    const float* mlp_w1   = (const float*)d_in[10];
    const float* mlp_b1   = (const float*)d_in[11];
    const float* mlp_w2   = (const float*)d_in[12];
    const float* mlp_b2   = (const float*)d_in[13];
    float* out = (float*)d_out;

    float *qkvb, *att, *x1, *hbuf, *wq, *wp, *w1, *w2;
    float2 *st1, *st2;
    cudaGetSymbolAddress((void**)&qkvb, g_qkv);
    cudaGetSymbolAddress((void**)&att,  g_att);
    cudaGetSymbolAddress((void**)&x1,   g_x1);
    cudaGetSymbolAddress((void**)&hbuf, g_h);
    cudaGetSymbolAddress((void**)&st1,  g_st1);
    cudaGetSymbolAddress((void**)&st2,  g_st2);
    cudaGetSymbolAddress((void**)&wq,   g_wq);
    cudaGetSymbolAddress((void**)&wp,   g_wp);
    cudaGetSymbolAddress((void**)&w1,   g_w1);
    cudaGetSymbolAddress((void**)&w2,   g_w2);

    const int SMEM   = 2 * 2 * 128 * LDK * 4;          // 73728 B (cp.async kernels)
    const int SMEML  = SMEM + 2 * 256 * 4;             // + g/b staging (LN kernels)
    cudaFuncSetAttribute(mma_gemm<1, 256,  256>, cudaFuncAttributeMaxDynamicSharedMemorySize, SMEM);
    cudaFuncSetAttribute(mma_gemm<3, 1024, 256>, cudaFuncAttributeMaxDynamicSharedMemorySize, SMEM);
    cudaFuncSetAttribute(mma_gemm_ln<0, 1, 256,  768>, cudaFuncAttributeMaxDynamicSharedMemorySize, SMEML);
    cudaFuncSetAttribute(mma_gemm_ln<2, 2, 256, 1024>, cudaFuncAttributeMaxDynamicSharedMemorySize, SMEML);

    // weight transposes + tf32 rounding (tiny)
    transpose_kernel<<<dim3(768 / 32, 256 / 32),  dim3(32, 8)>>>(qkv_w,  wq, 256, 768);
    transpose_kernel<<<dim3(256 / 32, 256 / 32),  dim3(32, 8)>>>(proj_w, wp, 256, 256);
    transpose_kernel<<<dim3(1024 / 32, 256 / 32), dim3(32, 8)>>>(mlp_w1, w1, 256, 1024);
    transpose_kernel<<<dim3(256 / 32, 1024 / 32), dim3(32, 8)>>>(mlp_w2, w2, 1024, 256);

    // 1. LN1 stats
    ln_stats_kernel<<<TOK / 8, 256>>>(x, st1);
    // 2. QKV GEMM with fused LN1 + shift + window partition
    mma_gemm_ln<0, 1, 256, 768><<<dim3(768 / 128, TOK / 128), 256, SMEML>>>(
        x, wq, st1, ln1_g, ln1_b, qkv_b, qkvb);
    // 3. windowed attention (tf32-rounded out)
    attn_kernel<<<dim3(NWTOT, HEADS), 256>>>(qkvb, rel_bias, att);
    // 4. proj GEMM + window reverse + roll + residual
    mma_gemm<1, 256, 256><<<dim3(256 / 128, TOK / 128), 256, SMEM>>>(att, wp, proj_b, x1, x);
    // 5. LN2 stats
    ln_stats_kernel<<<TOK / 8, 256>>>(x1, st2);
    // 6. MLP1 GEMM with fused LN2 + GELU epilogue
    mma_gemm_ln<2, 2, 256, 1024><<<dim3(1024 / 128, TOK / 128), 256, SMEML>>>(
        x1, w1, st2, ln2_g, ln2_b, mlp_b1, hbuf);
    // 7. MLP2 + residual -> d_out
    mma_gemm<3, 1024, 256><<<dim3(256 / 128, TOK / 128), 256, SMEM>>>(hbuf, w2, mlp_b2, out, x1);
}

// round 6
// speedup vs baseline: 4.1239x; 1.3462x over previous
#include <cuda_runtime.h>
#include <cuda_fp16.h>
#include <math.h>
#include <cstdint>

// ---------------- problem constants ----------------
#define TOK    100352          // 32 * 56 * 56 tokens
#define CC     256
#define HEADS  8
#define HD     32
#define WS     7
#define NWIN   49
#define MLPD   1024
#define HH     56
#define WW     56
#define SSH    3
#define NWB    64
#define NWTOT  2048
#define ATT_SCALE 0.17677669529663687f
#define LN_EPS 1e-5f

// ---------------- scratch (static device globals; no allocation) ----------------
__device__ __half g_qkv [(size_t)TOK * 3 * CC];
__device__ __half g_att [(size_t)TOK * CC];
__device__ float  g_x1  [(size_t)TOK * CC];
__device__ __half g_h   [(size_t)TOK * MLPD];
__device__ float2 g_st1[TOK];   // LN1 stats {mu, rsig} of x
__device__ float2 g_st2[TOK];   // LN2 stats of x1
// transposed weights [N,K] row-major, fp16
__device__ __half g_wq [768 * 256];
__device__ __half g_wp [256 * 256];
__device__ __half g_w1 [1024 * 256];
__device__ __half g_w2 [256 * 1024];

// ---------------- helpers ----------------
__device__ __forceinline__ uint32_t smem_u32(const void* p) {
    uint32_t a;
    asm("{ .reg .u64 t; cvta.to.shared.u64 t, %1; cvt.u32.u64 %0, t; }" : "=r"(a) : "l"(p));
    return a;
}
__device__ __forceinline__ void cp_async16(uint32_t dst, const void* src) {
    asm volatile("cp.async.cg.shared.global [%0], [%1], 16;" :: "r"(dst), "l"(src));
}
#define CP_COMMIT() asm volatile("cp.async.commit_group;" ::: "memory")

// m16n8k16 fp16 MMA, fp32 accumulate
__device__ __forceinline__ void mma_f16(float* c,
                                        uint32_t a0, uint32_t a1, uint32_t a2, uint32_t a3,
                                        uint32_t b0, uint32_t b1) {
    asm volatile(
        "mma.sync.aligned.m16n8k16.row.col.f32.f16.f16.f32 "
        "{%0,%1,%2,%3}, {%4,%5,%6,%7}, {%8,%9}, {%0,%1,%2,%3};"
        : "+f"(c[0]), "+f"(c[1]), "+f"(c[2]), "+f"(c[3])
        : "r"(a0), "r"(a1), "r"(a2), "r"(a3), "r"(b0), "r"(b1));
}

#define LDKH 40   // padded K stride (halves) per SMEM row; bank = 20*row + t4 -> conflict-free

// MMA over one 32-half K chunk (2 k-steps of 16)
__device__ __forceinline__ void chunk_mma(const __half* As, const __half* Bs,
                                          int wm, int wn, int g, int t4,
                                          float acc[4][4][4]) {
    #pragma unroll
    for (int ks = 0; ks < 2; ks++) {
        const int kb = ks * 16;
        uint32_t bf[4][2];
        #pragma unroll
        for (int ni = 0; ni < 4; ni++) {
            const __half* bp = Bs + (wn + ni * 8 + g) * LDKH + kb + t4 * 2;
            bf[ni][0] = *reinterpret_cast<const uint32_t*>(bp);
            bf[ni][1] = *reinterpret_cast<const uint32_t*>(bp + 8);
        }
        #pragma unroll
        for (int mi = 0; mi < 4; mi++) {
            const __half* ap = As + (wm + mi * 16 + g) * LDKH + kb + t4 * 2;
            uint32_t a0 = *reinterpret_cast<const uint32_t*>(ap);
            uint32_t a1 = *reinterpret_cast<const uint32_t*>(ap + 8 * LDKH);
            uint32_t a2 = *reinterpret_cast<const uint32_t*>(ap + 8);
            uint32_t a3 = *reinterpret_cast<const uint32_t*>(ap + 8 * LDKH + 8);
            #pragma unroll
            for (int ni = 0; ni < 4; ni++)
                mma_f16(acc[mi][ni], a0, a1, a2, a3, bf[ni][0], bf[ni][1]);
        }
    }
}

// shared epilogue. MODE 0: half out = acc+bias (QKV)
// MODE 1: float out = res+acc+bias, window-reverse scatter (proj)
// MODE 2: half out = gelu(acc+bias) (MLP1)
// MODE 3: float out = res+acc+bias (MLP2)
template<int MODE, int NDIM>
__device__ __forceinline__ void gemm_epilogue(float acc[4][4][4],
                                              int m0, int n0, int wm, int wn, int g, int t4,
                                              const float* __restrict__ bias,
                                              void* __restrict__ OutV,
                                              const float* __restrict__ res) {
    #pragma unroll
    for (int mi = 0; mi < 4; mi++) {
        #pragma unroll
        for (int h = 0; h < 2; h++) {
            int m = m0 + wm + mi * 16 + g + h * 8;
            size_t drow;
            if (MODE == 1) {
                int w = m / NWIN, ntok = m % NWIN;
                int bb2 = w / NWB, wi = w % NWB;
                int wy = wi >> 3, wx = wi & 7;
                int hy = wy * WS + ntok / WS, hx = wx * WS + ntok % WS;
                int oy = (hy + SSH) % HH, ox = (hx + SSH) % WW;
                drow = ((size_t)bb2 * HH * WW + oy * WW + ox) * CC;
            } else {
                drow = (size_t)m * NDIM;
            }
            #pragma unroll
            for (int ni = 0; ni < 4; ni++) {
                int n = n0 + wn + ni * 8 + 2 * t4;
                float2 bv = *reinterpret_cast<const float2*>(bias + n);
                float vx = acc[mi][ni][2 * h + 0] + bv.x;
                float vy = acc[mi][ni][2 * h + 1] + bv.y;
                if (MODE == 1 || MODE == 3) {
                    float2 r = *reinterpret_cast<const float2*>(res + drow + n);
                    float2 o = { vx + r.x, vy + r.y };
                    *reinterpret_cast<float2*>((float*)OutV + drow + n) = o;
                } else {
                    if (MODE == 2) {
                        vx = 0.5f * vx * (1.0f + erff(vx * 0.70710678118654752f));
                        vy = 0.5f * vy * (1.0f + erff(vy * 0.70710678118654752f));
                    }
                    *reinterpret_cast<__half2*>((__half*)OutV + drow + n) =
                        __floats2half2_rn(vx, vy);
                }
            }
        }
    }
}

// ---------------- cp.async fp16 GEMM (A half in global): proj / MLP2 ----------------
template<int MODE, int KDIM, int NDIM>
__global__ __launch_bounds__(256)
void mma_gemm(const __half* __restrict__ A, const __half* __restrict__ Wt,
              const float* __restrict__ bias, void* __restrict__ Out,
              const float* __restrict__ res)
{
    extern __shared__ char smraw[];
    __half* sm = reinterpret_cast<__half*>(smraw);
    const uint32_t sbase = smem_u32(smraw);

    const int tid  = threadIdx.x;
    const int wid  = tid >> 5, lane = tid & 31;
    const int g    = lane >> 2, t4 = lane & 3;
    const int wm   = (wid & 1) * 64;
    const int wn   = (wid >> 1) * 32;
    const int m0   = blockIdx.y * 128;
    const int n0   = blockIdx.x * 128;

    constexpr int NC = KDIM / 32;
    constexpr int STAGE = 2 * 128 * LDKH;          // halves per stage (A+B)

    auto load_chunk = [&](int c, int s) {
        const int k0 = c * 32;
        uint32_t sa = sbase + (uint32_t)(s * STAGE) * 2u;
        uint32_t sb2 = sa + 128u * LDKH * 2u;
        #pragma unroll
        for (int t = 0; t < 2; t++) {
            int f = t * 256 + tid;           // 0..511
            int row = f >> 2, seg = f & 3;   // 4 x 16B segments = 32 halves
            cp_async16(sa  + (uint32_t)(row * LDKH) * 2u + seg * 16,
                       A  + (size_t)(m0 + row) * KDIM + k0 + seg * 8);
            cp_async16(sb2 + (uint32_t)(row * LDKH) * 2u + seg * 16,
                       Wt + (size_t)(n0 + row) * KDIM + k0 + seg * 8);
        }
        CP_COMMIT();
    };

    float acc[4][4][4];
    #pragma unroll
    for (int i = 0; i < 4; i++)
        #pragma unroll
        for (int j = 0; j < 4; j++)
            #pragma unroll
            for (int e = 0; e < 4; e++) acc[i][j][e] = 0.0f;

    load_chunk(0, 0);
    if (NC > 1) load_chunk(1, 1);

    for (int c = 0; c < NC; c++) {
        if (c + 1 < NC) asm volatile("cp.async.wait_group 1;" ::: "memory");
        else            asm volatile("cp.async.wait_group 0;" ::: "memory");
        __syncthreads();
        const __half* As = sm + (c & 1) * STAGE;
        const __half* Bs = As + 128 * LDKH;
        chunk_mma(As, Bs, wm, wn, g, t4, acc);
        if (c + 2 < NC) {
            __syncthreads();
            load_chunk(c + 2, c & 1);
        }
    }
    gemm_epilogue<MODE, NDIM>(acc, m0, n0, wm, wn, g, t4, bias, Out, res);
}

// ---------------- LN-fused fp16 GEMM (LDG fp32 -> normalize -> fp16 -> STS): QKV / MLP1 ----------------
// LNMODE 1: shift-gather LN from x (QKV)    LNMODE 2: plain LN (MLP1)
template<int MODE, int LNMODE, int KDIM, int NDIM>
__global__ __launch_bounds__(256)
void mma_gemm_ln(const float* __restrict__ X, const __half* __restrict__ Wt,
                 const float2* __restrict__ stats,
                 const float* __restrict__ lng, const float* __restrict__ lnb,
                 const float* __restrict__ bias, void* __restrict__ Out)
{
    extern __shared__ char smraw[];
    __half* sm = reinterpret_cast<__half*>(smraw);
    constexpr int STAGE = 2 * 128 * LDKH;             // halves
    float* gS = reinterpret_cast<float*>(smraw + 2 * STAGE * 2);
    float* bS = gS + KDIM;

    const int tid  = threadIdx.x;
    const int wid  = tid >> 5, lane = tid & 31;
    const int g    = lane >> 2, t4 = lane & 3;
    const int wm   = (wid & 1) * 64;
    const int wn   = (wid >> 1) * 32;
    const int m0   = blockIdx.y * 128;
    const int n0   = blockIdx.x * 128;

    constexpr int NC = KDIM / 32;

    if (tid < KDIM) { gS[tid] = lng[tid]; bS[tid] = lnb[tid]; }

    // per-thread fixed (row, cg) slots: 4 rows per thread, 8 threads per row (32 elems)
    int rowA[4], srcA[4];
    float2 stA[4];
    #pragma unroll
    for (int t = 0; t < 4; t++) {
        int f = t * 256 + tid;
        int row = f >> 3;
        rowA[t] = row;
        int m = m0 + row;
        int src;
        if (LNMODE == 1) {
            int w = m / NWIN, n = m % NWIN;
            int bb = w >> 6, wi = w & 63;
            int wy = wi >> 3, wx = wi & 7;
            int hy = wy * WS + n / WS, hx = wx * WS + n % WS;
            int sy = hy + SSH; if (sy >= HH) sy -= HH;
            int sx = hx + SSH; if (sx >= WW) sx -= WW;
            src = bb * (HH * WW) + sy * WW + sx;
        } else {
            src = m;
        }
        srcA[t] = src;
        stA[t] = __ldg(&stats[src]);
    }
    const int cg = tid & 7;

    float4 ra[4];
    uint2 rb[4];
    auto ldg_chunk = [&](int c) {
        const int k0 = c * 32;
        #pragma unroll
        for (int t = 0; t < 4; t++) {
            ra[t] = *reinterpret_cast<const float4*>(X + (size_t)srcA[t] * KDIM + k0 + cg * 4);
            rb[t] = *reinterpret_cast<const uint2*>(Wt + (size_t)(n0 + rowA[t]) * KDIM + k0 + cg * 4);
        }
    };
    auto sts_chunk = [&](int c, int s) {
        const int k0 = c * 32;
        __half* As = sm + s * STAGE;
        __half* Bs = As + 128 * LDKH;
        const float4 g4 = *reinterpret_cast<const float4*>(gS + k0 + cg * 4);
        const float4 b4 = *reinterpret_cast<const float4*>(bS + k0 + cg * 4);
        #pragma unroll
        for (int t = 0; t < 4; t++) {
            float mu = stA[t].x, inv = stA[t].y;
            float4 v = ra[t];
            __half2 h01 = __floats2half2_rn((v.x - mu) * inv * g4.x + b4.x,
                                            (v.y - mu) * inv * g4.y + b4.y);
            __half2 h23 = __floats2half2_rn((v.z - mu) * inv * g4.z + b4.z,
                                            (v.w - mu) * inv * g4.w + b4.w);
            uint2 pk = { *reinterpret_cast<uint32_t*>(&h01), *reinterpret_cast<uint32_t*>(&h23) };
            *reinterpret_cast<uint2*>(As + rowA[t] * LDKH + cg * 4) = pk;
            *reinterpret_cast<uint2*>(Bs + rowA[t] * LDKH + cg * 4) = rb[t];
        }
    };

    float acc[4][4][4];
    #pragma unroll
    for (int i = 0; i < 4; i++)
        #pragma unroll
        for (int j = 0; j < 4; j++)
            #pragma unroll
            for (int e = 0; e < 4; e++) acc[i][j][e] = 0.0f;

    ldg_chunk(0);
    __syncthreads();        // gS/bS visible before first sts_chunk
    sts_chunk(0, 0);
    if (NC > 1) ldg_chunk(1);
    __syncthreads();        // stage 0 fully written

    for (int c = 0; c < NC; c++) {
        int s = c & 1;
        chunk_mma(sm + s * STAGE, sm + s * STAGE + 128 * LDKH, wm, wn, g, t4, acc);
        if (c + 1 < NC) {
            __syncthreads();                // all warps done reading stage s^1
            sts_chunk(c + 1, s ^ 1);
            if (c + 2 < NC) ldg_chunk(c + 2);
            __syncthreads();                // stage s^1 now holds chunk c+1
        }
    }
    gemm_epilogue<MODE, NDIM>(acc, m0, n0, wm, wn, g, t4, bias, Out, nullptr);
}

// ---------------- LN stats: warp per token -> {mu, rsig} ----------------
__global__ __launch_bounds__(256)
void ln_stats_kernel(const float* __restrict__ x, float2* __restrict__ st)
{
    int t = blockIdx.x * 8 + (threadIdx.x >> 5);
    int lane = threadIdx.x & 31;
    const float4* rp = reinterpret_cast<const float4*>(x + (size_t)t * CC);
    float4 a = rp[lane], c = rp[lane + 32];
    float s  = a.x + a.y + a.z + a.w + c.x + c.y + c.z + c.w;
    float s2 = a.x * a.x + a.y * a.y + a.z * a.z + a.w * a.w
             + c.x * c.x + c.y * c.y + c.z * c.z + c.w * c.w;
    #pragma unroll
    for (int o = 16; o > 0; o >>= 1) {
        s  += __shfl_xor_sync(0xffffffff, s, o);
        s2 += __shfl_xor_sync(0xffffffff, s2, o);
    }
    if (lane == 0) {
        float mu  = s * (1.0f / CC);
        float var = s2 * (1.0f / CC) - mu * mu;
        st[t] = make_float2(mu, rsqrtf(var + LN_EPS));
    }
}

// ---------------- weight transpose + fp16 round: W[K,N] fp32 -> Wt[N,K] half ----------------
__global__ void transpose_kernel(const float* __restrict__ W, __half* __restrict__ Wt, int K, int N)
{
    __shared__ float t[32][33];
    int k0 = blockIdx.y * 32, n0 = blockIdx.x * 32;
    int tx = threadIdx.x, ty = threadIdx.y;
    for (int i = ty; i < 32; i += 8) t[i][tx] = W[(size_t)(k0 + i) * N + n0 + tx];
    __syncthreads();
    for (int i = ty; i < 32; i += 8) Wt[(size_t)(n0 + i) * K + k0 + tx] = __float2half_rn(t[tx][i]);
}

// ---------------- windowed attention (half I/O, fp32 math, padded SMEM) ----------------
__global__ __launch_bounds__(256)
void attn_kernel(const __half* __restrict__ qkv,
                 const float* __restrict__ rel_bias,
                 __half* __restrict__ out)
{
    int w    = blockIdx.x;
    int head = blockIdx.y;
    int tid  = threadIdx.x;

    __shared__ float q[NWIN][HD];          // broadcast reads -> no pad needed
    __shared__ float k[NWIN][HD + 1];      // pad: conflict-free k[j][d] with lanes on j
    __shared__ float v[NWIN][HD + 1];
    __shared__ float s[NWIN][52];
    __shared__ float bias_s[169];

    for (int i = tid; i < 169; i += 256)
        bias_s[i] = rel_bias[i * HEADS + head];

    for (int idx = tid; idx < NWIN * (HD / 2); idx += 256) {
        int n = idx >> 4, dp = idx & 15, d = dp * 2;
        size_t base = ((size_t)(w * NWIN + n)) * (3 * CC) + head * HD + d;
        float2 qf = __half22float2(*reinterpret_cast<const __half2*>(qkv + base));
        float2 kf = __half22float2(*reinterpret_cast<const __half2*>(qkv + base + CC));
        float2 vf = __half22float2(*reinterpret_cast<const __half2*>(qkv + base + 2 * CC));
        q[n][d] = qf.x; q[n][d + 1] = qf.y;
        k[n][d] = kf.x; k[n][d + 1] = kf.y;
        v[n][d] = vf.x; v[n][d + 1] = vf.y;
    }
    __syncthreads();

    int wi = w % NWB;
    int wy = wi >> 3, wx = wi & 7;

    for (int idx = tid; idx < NWIN * NWIN; idx += 256) {
        int i = idx / NWIN, j = idx % NWIN;
        float dot = 0.0f;
        #pragma unroll
        for (int d = 0; d < HD; d++) dot += q[i][d] * k[j][d];
        int yi = i / WS, xi = i % WS, yj = j / WS, xj = j % WS;
        int rp = (yi - yj + WS - 1) * (2 * WS - 1) + (xi - xj + WS - 1);
        int gyi = wy * WS + yi, gxi = wx * WS + xi;
        int gyj = wy * WS + yj, gxj = wx * WS + xj;
        int ri = (gyi < HH - WS ? 0 : (gyi < HH - SSH ? 1 : 2)) * 3
               + (gxi < WW - WS ? 0 : (gxi < WW - SSH ? 1 : 2));
        int rj = (gyj < HH - WS ? 0 : (gyj < HH - SSH ? 1 : 2)) * 3
               + (gxj < WW - WS ? 0 : (gxj < WW - SSH ? 1 : 2));
        float mask = (ri != rj) ? -100.0f : 0.0f;
        s[i][j] = dot * ATT_SCALE + bias_s[rp] + mask;
    }
    __syncthreads();

    int warp = tid >> 5, lane = tid & 31;
    for (int i = warp; i < NWIN; i += 8) {
        float m = -1e30f;
        for (int j = lane; j < NWIN; j += 32) m = fmaxf(m, s[i][j]);
        #pragma unroll
        for (int o = 16; o > 0; o >>= 1) m = fmaxf(m, __shfl_xor_sync(0xffffffff, m, o));
        float sum = 0.0f;
        for (int j = lane; j < NWIN; j += 32) { float e = __expf(s[i][j] - m); s[i][j] = e; sum += e; }
        #pragma unroll
        for (int o = 16; o > 0; o >>= 1) sum += __shfl_xor_sync(0xffffffff, sum, o);
        float inv = 1.0f / sum;
        for (int j = lane; j < NWIN; j += 32) s[i][j] *= inv;
    }
    __syncthreads();

    for (int idx = tid; idx < NWIN * HD; idx += 256) {
        int i = idx >> 5, d = idx & 31;
        float acc = 0.0f;
        #pragma unroll
        for (int j = 0; j < NWIN; j++) acc += s[i][j] * v[j][d];
        out[((size_t)(w * NWIN + i)) * CC + head * HD + d] = __float2half_rn(acc);
    }
}

// ---------------- launcher ----------------
extern "C" void kernel_launch(void* const* d_in, const int* in_sizes, int n_in,
                              void* d_out, int out_size)
{
    (void)in_sizes; (void)n_in; (void)out_size;
    const float* x        = (const float*)d_in[0];
    const float* qkv_w    = (const float*)d_in[1];
    const float* qkv_b    = (const float*)d_in[2];
    const float* proj_w   = (const float*)d_in[3];
    const float* proj_b   = (const float*)d_in[4];
    const float* rel_bias = (const float*)d_in[5];
    const float* ln1_g    = (const float*)d_in[6];
    const float* ln1_b    = (const float*)d_in[7];
    const float* ln2_g    = (const float*)d_in[8];
    const float* ln2_b    = (const float*)d_in[9];
    const float* mlp_w1   = (const float*)d_in[10];
    const float* mlp_b1   = (const float*)d_in[11];
    const float* mlp_w2   = (const float*)d_in[12];
    const float* mlp_b2   = (const float*)d_in[13];
    float* out = (float*)d_out;

    __half *qkvb, *att, *hbuf, *wq, *wp, *w1, *w2;
    float *x1;
    float2 *st1, *st2;
    cudaGetSymbolAddress((void**)&qkvb, g_qkv);
    cudaGetSymbolAddress((void**)&att,  g_att);
    cudaGetSymbolAddress((void**)&x1,   g_x1);
    cudaGetSymbolAddress((void**)&hbuf, g_h);
    cudaGetSymbolAddress((void**)&st1,  g_st1);
    cudaGetSymbolAddress((void**)&st2,  g_st2);
    cudaGetSymbolAddress((void**)&wq,   g_wq);
    cudaGetSymbolAddress((void**)&wp,   g_wp);
    cudaGetSymbolAddress((void**)&w1,   g_w1);
    cudaGetSymbolAddress((void**)&w2,   g_w2);

    const int SMEM  = 2 * 2 * 128 * LDKH * 2;          // 40960 B (cp.async kernels)
    const int SMEML = SMEM + 2 * 256 * 4;              // + LN g/b staging
    cudaFuncSetAttribute(mma_gemm<1, 256,  256>, cudaFuncAttributeMaxDynamicSharedMemorySize, SMEM);
    cudaFuncSetAttribute(mma_gemm<3, 1024, 256>, cudaFuncAttributeMaxDynamicSharedMemorySize, SMEM);
    cudaFuncSetAttribute(mma_gemm_ln<0, 1, 256,  768>, cudaFuncAttributeMaxDynamicSharedMemorySize, SMEML);
    cudaFuncSetAttribute(mma_gemm_ln<2, 2, 256, 1024>, cudaFuncAttributeMaxDynamicSharedMemorySize, SMEML);

    // weight transposes + fp16 rounding (tiny)
    transpose_kernel<<<dim3(768 / 32, 256 / 32),  dim3(32, 8)>>>(qkv_w,  wq, 256, 768);
    transpose_kernel<<<dim3(256 / 32, 256 / 32),  dim3(32, 8)>>>(proj_w, wp, 256, 256);
    transpose_kernel<<<dim3(1024 / 32, 256 / 32), dim3(32, 8)>>>(mlp_w1, w1, 256, 1024);
    transpose_kernel<<<dim3(256 / 32, 1024 / 32), dim3(32, 8)>>>(mlp_w2, w2, 1024, 256);

    // 1. LN1 stats
    ln_stats_kernel<<<TOK / 8, 256>>>(x, st1);
    // 2. QKV GEMM with fused LN1 + shift + window partition (half out)
    mma_gemm_ln<0, 1, 256, 768><<<dim3(768 / 128, TOK / 128), 256, SMEML>>>(
        x, wq, st1, ln1_g, ln1_b, qkv_b, qkvb);
    // 3. windowed attention (half in/out)
    attn_kernel<<<dim3(NWTOT, HEADS), 256>>>(qkvb, rel_bias, att);
    // 4. proj GEMM + window reverse + roll + residual (float out)
    mma_gemm<1, 256, 256><<<dim3(256 / 128, TOK / 128), 256, SMEM>>>(att, wp, proj_b, x1, x);
    // 5. LN2 stats
    ln_stats_kernel<<<TOK / 8, 256>>>(x1, st2);
    // 6. MLP1 GEMM with fused LN2 + GELU epilogue (half out)
    mma_gemm_ln<2, 2, 256, 1024><<<dim3(1024 / 128, TOK / 128), 256, SMEML>>>(
        x1, w1, st2, ln2_g, ln2_b, mlp_b1, hbuf);
    // 7. MLP2 + residual -> d_out (float out)
    mma_gemm<3, 1024, 256><<<dim3(256 / 128, TOK / 128), 256, SMEM>>>(hbuf, w2, mlp_b2, out, x1);
}

// round 7
// speedup vs baseline: 4.3054x; 1.0440x over previous
#include <cuda_runtime.h>
#include <cuda_fp16.h>
#include <math.h>
#include <cstdint>

// ---------------- problem constants ----------------
#define TOK    100352          // 32 * 56 * 56 tokens
#define CC     256
#define HEADS  8
#define HD     32
#define WS     7
#define NWIN   49
#define MLPD   1024
#define HH     56
#define WW     56
#define SSH    3
#define NWB    64
#define NWTOT  2048
#define ATT_SCALE 0.17677669529663687f
#define LN_EPS 1e-5f

// ---------------- scratch (static device globals; no allocation) ----------------
__device__ __half g_qkv [(size_t)TOK * 3 * CC];
__device__ __half g_att [(size_t)TOK * CC];
__device__ float  g_x1  [(size_t)TOK * CC];
__device__ __half g_h   [(size_t)TOK * MLPD];
__device__ float2 g_st1[TOK];   // LN1 stats {mu, rsig} of x
__device__ float2 g_st2[TOK];   // LN2 stats of x1
// transposed weights [N,K] row-major, fp16
__device__ __half g_wq [768 * 256];
__device__ __half g_wp [256 * 256];
__device__ __half g_w1 [1024 * 256];
__device__ __half g_w2 [256 * 1024];

// ---------------- helpers ----------------
__device__ __forceinline__ uint32_t smem_u32(const void* p) {
    uint32_t a;
    asm("{ .reg .u64 t; cvta.to.shared.u64 t, %1; cvt.u32.u64 %0, t; }" : "=r"(a) : "l"(p));
    return a;
}
__device__ __forceinline__ void cp_async16(uint32_t dst, const void* src) {
    asm volatile("cp.async.cg.shared.global [%0], [%1], 16;" :: "r"(dst), "l"(src));
}
#define CP_COMMIT() asm volatile("cp.async.commit_group;" ::: "memory")

// m16n8k16 fp16 MMA, fp32 accumulate
__device__ __forceinline__ void mma_f16(float* c,
                                        uint32_t a0, uint32_t a1, uint32_t a2, uint32_t a3,
                                        uint32_t b0, uint32_t b1) {
    asm volatile(
        "mma.sync.aligned.m16n8k16.row.col.f32.f16.f16.f32 "
        "{%0,%1,%2,%3}, {%4,%5,%6,%7}, {%8,%9}, {%0,%1,%2,%3};"
        : "+f"(c[0]), "+f"(c[1]), "+f"(c[2]), "+f"(c[3])
        : "r"(a0), "r"(a1), "r"(a2), "r"(a3), "r"(b0), "r"(b1));
}

// generic K-step MMA over CH-half chunk with row stride LDX (halves)
template<int LDX, int CH>
__device__ __forceinline__ void chunk_mma(const __half* As, const __half* Bs,
                                          int wm, int wn, int g, int t4,
                                          float acc[4][4][4]) {
    #pragma unroll
    for (int ks = 0; ks < CH / 16; ks++) {
        const int kb = ks * 16;
        uint32_t bf[4][2];
        #pragma unroll
        for (int ni = 0; ni < 4; ni++) {
            const __half* bp = Bs + (wn + ni * 8 + g) * LDX + kb + t4 * 2;
            bf[ni][0] = *reinterpret_cast<const uint32_t*>(bp);
            bf[ni][1] = *reinterpret_cast<const uint32_t*>(bp + 8);
        }
        #pragma unroll
        for (int mi = 0; mi < 4; mi++) {
            const __half* ap = As + (wm + mi * 16 + g) * LDX + kb + t4 * 2;
            uint32_t a0 = *reinterpret_cast<const uint32_t*>(ap);
            uint32_t a1 = *reinterpret_cast<const uint32_t*>(ap + 8 * LDX);
            uint32_t a2 = *reinterpret_cast<const uint32_t*>(ap + 8);
            uint32_t a3 = *reinterpret_cast<const uint32_t*>(ap + 8 * LDX + 8);
            #pragma unroll
            for (int ni = 0; ni < 4; ni++)
                mma_f16(acc[mi][ni], a0, a1, a2, a3, bf[ni][0], bf[ni][1]);
        }
    }
}

// shared epilogue. MODE 0: half out (QKV)  MODE 1: float res+scatter (proj)
// MODE 2: half gelu out (MLP1)  MODE 3: float res out (MLP2)
template<int MODE, int NDIM>
__device__ __forceinline__ void gemm_epilogue(float acc[4][4][4],
                                              int m0, int n0, int wm, int wn, int g, int t4,
                                              const float* __restrict__ bias,
                                              void* __restrict__ OutV,
                                              const float* __restrict__ res) {
    #pragma unroll
    for (int mi = 0; mi < 4; mi++) {
        #pragma unroll
        for (int h = 0; h < 2; h++) {
            int m = m0 + wm + mi * 16 + g + h * 8;
            size_t drow;
            if (MODE == 1) {
                int w = m / NWIN, ntok = m % NWIN;
                int bb2 = w / NWB, wi = w % NWB;
                int wy = wi >> 3, wx = wi & 7;
                int hy = wy * WS + ntok / WS, hx = wx * WS + ntok % WS;
                int oy = (hy + SSH) % HH, ox = (hx + SSH) % WW;
                drow = ((size_t)bb2 * HH * WW + oy * WW + ox) * CC;
            } else {
                drow = (size_t)m * NDIM;
            }
            #pragma unroll
            for (int ni = 0; ni < 4; ni++) {
                int n = n0 + wn + ni * 8 + 2 * t4;
                float2 bv = *reinterpret_cast<const float2*>(bias + n);
                float vx = acc[mi][ni][2 * h + 0] + bv.x;
                float vy = acc[mi][ni][2 * h + 1] + bv.y;
                if (MODE == 1 || MODE == 3) {
                    float2 r = *reinterpret_cast<const float2*>(res + drow + n);
                    float2 o = { vx + r.x, vy + r.y };
                    *reinterpret_cast<float2*>((float*)OutV + drow + n) = o;
                } else {
                    if (MODE == 2) {
                        vx = 0.5f * vx * (1.0f + erff(vx * 0.70710678118654752f));
                        vy = 0.5f * vy * (1.0f + erff(vy * 0.70710678118654752f));
                    }
                    *reinterpret_cast<__half2*>((__half*)OutV + drow + n) =
                        __floats2half2_rn(vx, vy);
                }
            }
        }
    }
}

// ---------------- cp.async fp16 GEMM, 64-half K chunks: proj / MLP2 ----------------
#define LDKH2 72
template<int MODE, int KDIM, int NDIM>
__global__ __launch_bounds__(256)
void mma_gemm(const __half* __restrict__ A, const __half* __restrict__ Wt,
              const float* __restrict__ bias, void* __restrict__ Out,
              const float* __restrict__ res)
{
    extern __shared__ char smraw[];
    __half* sm = reinterpret_cast<__half*>(smraw);
    const uint32_t sbase = smem_u32(smraw);

    const int tid  = threadIdx.x;
    const int wid  = tid >> 5, lane = tid & 31;
    const int g    = lane >> 2, t4 = lane & 3;
    const int wm   = (wid & 1) * 64;
    const int wn   = (wid >> 1) * 32;
    const int m0   = blockIdx.y * 128;
    const int n0   = blockIdx.x * 128;

    constexpr int NC = KDIM / 64;
    constexpr int STAGE = 2 * 128 * LDKH2;        // halves per stage (A+B)

    auto load_chunk = [&](int c, int s) {
        const int k0 = c * 64;
        uint32_t sa  = sbase + (uint32_t)(s * STAGE) * 2u;
        uint32_t sb2 = sa + 128u * LDKH2 * 2u;
        #pragma unroll
        for (int t = 0; t < 4; t++) {
            int f = t * 256 + tid;           // 0..1023
            int row = f >> 3, seg = f & 7;   // 8 x 16B segments = 64 halves
            cp_async16(sa  + (uint32_t)(row * LDKH2) * 2u + seg * 16,
                       A  + (size_t)(m0 + row) * KDIM + k0 + seg * 8);
            cp_async16(sb2 + (uint32_t)(row * LDKH2) * 2u + seg * 16,
                       Wt + (size_t)(n0 + row) * KDIM + k0 + seg * 8);
        }
        CP_COMMIT();
    };

    float acc[4][4][4];
    #pragma unroll
    for (int i = 0; i < 4; i++)
        #pragma unroll
        for (int j = 0; j < 4; j++)
            #pragma unroll
            for (int e = 0; e < 4; e++) acc[i][j][e] = 0.0f;

    load_chunk(0, 0);
    if (NC > 1) load_chunk(1, 1);

    for (int c = 0; c < NC; c++) {
        if (c + 1 < NC) asm volatile("cp.async.wait_group 1;" ::: "memory");
        else            asm volatile("cp.async.wait_group 0;" ::: "memory");
        __syncthreads();
        const __half* As = sm + (c & 1) * STAGE;
        const __half* Bs = As + 128 * LDKH2;
        chunk_mma<LDKH2, 64>(As, Bs, wm, wn, g, t4, acc);
        if (c + 2 < NC) {
            __syncthreads();
            load_chunk(c + 2, c & 1);
        }
    }
    gemm_epilogue<MODE, NDIM>(acc, m0, n0, wm, wn, g, t4, bias, Out, res);
}

// ---------------- LN-fused fp16 GEMM (32-half chunks): QKV / MLP1 ----------------
#define LDKH 40
// LNMODE 1: shift-gather LN from x (QKV)    LNMODE 2: plain LN (MLP1)
template<int MODE, int LNMODE, int KDIM, int NDIM>
__global__ __launch_bounds__(256)
void mma_gemm_ln(const float* __restrict__ X, const __half* __restrict__ Wt,
                 const float2* __restrict__ stats,
                 const float* __restrict__ lng, const float* __restrict__ lnb,
                 const float* __restrict__ bias, void* __restrict__ Out)
{
    extern __shared__ char smraw[];
    __half* sm = reinterpret_cast<__half*>(smraw);
    constexpr int STAGE = 2 * 128 * LDKH;             // halves
    float* gS = reinterpret_cast<float*>(smraw + 2 * STAGE * 2);
    float* bS = gS + KDIM;

    const int tid  = threadIdx.x;
    const int wid  = tid >> 5, lane = tid & 31;
    const int g    = lane >> 2, t4 = lane & 3;
    const int wm   = (wid & 1) * 64;
    const int wn   = (wid >> 1) * 32;
    const int m0   = blockIdx.y * 128;
    const int n0   = blockIdx.x * 128;

    constexpr int NC = KDIM / 32;

    if (tid < KDIM) { gS[tid] = lng[tid]; bS[tid] = lnb[tid]; }

    int rowA[4], srcA[4];
    float2 stA[4];
    #pragma unroll
    for (int t = 0; t < 4; t++) {
        int f = t * 256 + tid;
        int row = f >> 3;
        rowA[t] = row;
        int m = m0 + row;
        int src;
        if (LNMODE == 1) {
            int w = m / NWIN, n = m % NWIN;
            int bb = w >> 6, wi = w & 63;
            int wy = wi >> 3, wx = wi & 7;
            int hy = wy * WS + n / WS, hx = wx * WS + n % WS;
            int sy = hy + SSH; if (sy >= HH) sy -= HH;
            int sx = hx + SSH; if (sx >= WW) sx -= WW;
            src = bb * (HH * WW) + sy * WW + sx;
        } else {
            src = m;
        }
        srcA[t] = src;
        stA[t] = __ldg(&stats[src]);
    }
    const int cg = tid & 7;

    float4 ra[4];
    uint2 rb[4];
    auto ldg_chunk = [&](int c) {
        const int k0 = c * 32;
        #pragma unroll
        for (int t = 0; t < 4; t++) {
            ra[t] = *reinterpret_cast<const float4*>(X + (size_t)srcA[t] * KDIM + k0 + cg * 4);
            rb[t] = *reinterpret_cast<const uint2*>(Wt + (size_t)(n0 + rowA[t]) * KDIM + k0 + cg * 4);
        }
    };
    auto sts_chunk = [&](int c, int s) {
        const int k0 = c * 32;
        __half* As = sm + s * STAGE;
        __half* Bs = As + 128 * LDKH;
        const float4 g4 = *reinterpret_cast<const float4*>(gS + k0 + cg * 4);
        const float4 b4 = *reinterpret_cast<const float4*>(bS + k0 + cg * 4);
        #pragma unroll
        for (int t = 0; t < 4; t++) {
            float mu = stA[t].x, inv = stA[t].y;
            float4 v = ra[t];
            __half2 h01 = __floats2half2_rn((v.x - mu) * inv * g4.x + b4.x,
                                            (v.y - mu) * inv * g4.y + b4.y);
            __half2 h23 = __floats2half2_rn((v.z - mu) * inv * g4.z + b4.z,
                                            (v.w - mu) * inv * g4.w + b4.w);
            uint2 pk = { *reinterpret_cast<uint32_t*>(&h01), *reinterpret_cast<uint32_t*>(&h23) };
            *reinterpret_cast<uint2*>(As + rowA[t] * LDKH + cg * 4) = pk;
            *reinterpret_cast<uint2*>(Bs + rowA[t] * LDKH + cg * 4) = rb[t];
        }
    };

    float acc[4][4][4];
    #pragma unroll
    for (int i = 0; i < 4; i++)
        #pragma unroll
        for (int j = 0; j < 4; j++)
            #pragma unroll
            for (int e = 0; e < 4; e++) acc[i][j][e] = 0.0f;

    ldg_chunk(0);
    __syncthreads();        // gS/bS visible before first sts_chunk
    sts_chunk(0, 0);
    if (NC > 1) ldg_chunk(1);
    __syncthreads();        // stage 0 fully written

    for (int c = 0; c < NC; c++) {
        int s = c & 1;
        chunk_mma<LDKH, 32>(sm + s * STAGE, sm + s * STAGE + 128 * LDKH, wm, wn, g, t4, acc);
        if (c + 1 < NC) {
            __syncthreads();
            sts_chunk(c + 1, s ^ 1);
            if (c + 2 < NC) ldg_chunk(c + 2);
            __syncthreads();
        }
    }
    gemm_epilogue<MODE, NDIM>(acc, m0, n0, wm, wn, g, t4, bias, Out, nullptr);
}

// ---------------- LN stats: warp per token -> {mu, rsig} ----------------
__global__ __launch_bounds__(256)
void ln_stats_kernel(const float* __restrict__ x, float2* __restrict__ st)
{
    int t = blockIdx.x * 8 + (threadIdx.x >> 5);
    int lane = threadIdx.x & 31;
    const float4* rp = reinterpret_cast<const float4*>(x + (size_t)t * CC);
    float4 a = rp[lane], c = rp[lane + 32];
    float s  = a.x + a.y + a.z + a.w + c.x + c.y + c.z + c.w;
    float s2 = a.x * a.x + a.y * a.y + a.z * a.z + a.w * a.w
             + c.x * c.x + c.y * c.y + c.z * c.z + c.w * c.w;
    #pragma unroll
    for (int o = 16; o > 0; o >>= 1) {
        s  += __shfl_xor_sync(0xffffffff, s, o);
        s2 += __shfl_xor_sync(0xffffffff, s2, o);
    }
    if (lane == 0) {
        float mu  = s * (1.0f / CC);
        float var = s2 * (1.0f / CC) - mu * mu;
        st[t] = make_float2(mu, rsqrtf(var + LN_EPS));
    }
}

// ---------------- weight transpose + fp16 round: W[K,N] fp32 -> Wt[N,K] half ----------------
__global__ void transpose_kernel(const float* __restrict__ W, __half* __restrict__ Wt, int K, int N)
{
    __shared__ float t[32][33];
    int k0 = blockIdx.y * 32, n0 = blockIdx.x * 32;
    int tx = threadIdx.x, ty = threadIdx.y;
    for (int i = ty; i < 32; i += 8) t[i][tx] = W[(size_t)(k0 + i) * N + n0 + tx];
    __syncthreads();
    for (int i = ty; i < 32; i += 8) Wt[(size_t)(n0 + i) * K + k0 + tx] = __float2half_rn(t[tx][i]);
}

// ---------------- windowed attention (half I/O, precomputed token codes) ----------------
__global__ __launch_bounds__(256)
void attn_kernel(const __half* __restrict__ qkv,
                 const float* __restrict__ rel_bias,
                 __half* __restrict__ out)
{
    int w    = blockIdx.x;
    int head = blockIdx.y;
    int tid  = threadIdx.x;

    __shared__ float q[NWIN][HD];
    __shared__ float k[NWIN][HD + 1];
    __shared__ float v[NWIN][HD + 1];
    __shared__ float s[NWIN][52];
    __shared__ float bias_s[169];
    __shared__ int   code[NWIN];      // (y*13+x) | region<<16

    for (int i = tid; i < 169; i += 256)
        bias_s[i] = rel_bias[i * HEADS + head];

    if (tid < NWIN) {
        int wi = w % NWB;
        int wy = wi >> 3, wx = wi & 7;
        int yi = tid / WS, xi = tid % WS;
        int gy = wy * WS + yi, gx = wx * WS + xi;
        int r = (gy < HH - WS ? 0 : (gy < HH - SSH ? 1 : 2)) * 3
              + (gx < WW - WS ? 0 : (gx < WW - SSH ? 1 : 2));
        code[tid] = (yi * 13 + xi) | (r << 16);
    }

    for (int idx = tid; idx < NWIN * (HD / 2); idx += 256) {
        int n = idx >> 4, dp = idx & 15, d = dp * 2;
        size_t base = ((size_t)(w * NWIN + n)) * (3 * CC) + head * HD + d;
        float2 qf = __half22float2(*reinterpret_cast<const __half2*>(qkv + base));
        float2 kf = __half22float2(*reinterpret_cast<const __half2*>(qkv + base + CC));
        float2 vf = __half22float2(*reinterpret_cast<const __half2*>(qkv + base + 2 * CC));
        q[n][d] = qf.x; q[n][d + 1] = qf.y;
        k[n][d] = kf.x; k[n][d + 1] = kf.y;
        v[n][d] = vf.x; v[n][d + 1] = vf.y;
    }
    __syncthreads();

    for (int idx = tid; idx < NWIN * NWIN; idx += 256) {
        int i = idx / NWIN, j = idx % NWIN;
        float dot = 0.0f;
        #pragma unroll
        for (int d = 0; d < HD; d++) dot += q[i][d] * k[j][d];
        int ci = code[i], cj = code[j];
        int rp = (ci & 0xffff) - (cj & 0xffff) + 84;
        float mask = ((ci ^ cj) & 0xffff0000) ? -100.0f : 0.0f;
        s[i][j] = dot * ATT_SCALE + bias_s[rp] + mask;
    }
    __syncthreads();

    int warp = tid >> 5, lane = tid & 31;
    for (int i = warp; i < NWIN; i += 8) {
        float m = -1e30f;
        for (int j = lane; j < NWIN; j += 32) m = fmaxf(m, s[i][j]);
        #pragma unroll
        for (int o = 16; o > 0; o >>= 1) m = fmaxf(m, __shfl_xor_sync(0xffffffff, m, o));
        float sum = 0.0f;
        for (int j = lane; j < NWIN; j += 32) { float e = __expf(s[i][j] - m); s[i][j] = e; sum += e; }
        #pragma unroll
        for (int o = 16; o > 0; o >>= 1) sum += __shfl_xor_sync(0xffffffff, sum, o);
        float inv = 1.0f / sum;
        for (int j = lane; j < NWIN; j += 32) s[i][j] *= inv;
    }
    __syncthreads();

    for (int idx = tid; idx < NWIN * HD; idx += 256) {
        int i = idx >> 5, d = idx & 31;
        float acc = 0.0f;
        #pragma unroll
        for (int j = 0; j < NWIN; j++) acc += s[i][j] * v[j][d];
        out[((size_t)(w * NWIN + i)) * CC + head * HD + d] = __float2half_rn(acc);
    }
}

// ---------------- launcher ----------------
extern "C" void kernel_launch(void* const* d_in, const int* in_sizes, int n_in,
                              void* d_out, int out_size)
{
    (void)in_sizes; (void)n_in; (void)out_size;
    const float* x        = (const float*)d_in[0];
    const float* qkv_w    = (const float*)d_in[1];
    const float* qkv_b    = (const float*)d_in[2];
    const float* proj_w   = (const float*)d_in[3];
    const float* proj_b   = (const float*)d_in[4];
    const float* rel_bias = (const float*)d_in[5];
    const float* ln1_g    = (const float*)d_in[6];
    const float* ln1_b    = (const float*)d_in[7];
    const float* ln2_g    = (const float*)d_in[8];
    const float* ln2_b    = (const float*)d_in[9];
    const float* mlp_w1   = (const float*)d_in[10];
    const float* mlp_b1   = (const float*)d_in[11];
    const float* mlp_w2   = (const float*)d_in[12];
    const float* mlp_b2   = (const float*)d_in[13];
    float* out = (float*)d_out;

    __half *qkvb, *att, *hbuf, *wq, *wp, *w1, *w2;
    float *x1;
    float2 *st1, *st2;
    cudaGetSymbolAddress((void**)&qkvb, g_qkv);
    cudaGetSymbolAddress((void**)&att,  g_att);
    cudaGetSymbolAddress((void**)&x1,   g_x1);
    cudaGetSymbolAddress((void**)&hbuf, g_h);
    cudaGetSymbolAddress((void**)&st1,  g_st1);
    cudaGetSymbolAddress((void**)&st2,  g_st2);
    cudaGetSymbolAddress((void**)&wq,   g_wq);
    cudaGetSymbolAddress((void**)&wp,   g_wp);
    cudaGetSymbolAddress((void**)&w1,   g_w1);
    cudaGetSymbolAddress((void**)&w2,   g_w2);

    const int SMEM2 = 2 * 2 * 128 * LDKH2 * 2;         // 73728 B (64-chunk cp.async)
    const int SMEML = 2 * 2 * 128 * LDKH * 2 + 2 * 256 * 4;  // 40960 + 2048 (LN kernels)
    cudaFuncSetAttribute(mma_gemm<1, 256,  256>, cudaFuncAttributeMaxDynamicSharedMemorySize, SMEM2);
    cudaFuncSetAttribute(mma_gemm<3, 1024, 256>, cudaFuncAttributeMaxDynamicSharedMemorySize, SMEM2);
    cudaFuncSetAttribute(mma_gemm_ln<0, 1, 256,  768>, cudaFuncAttributeMaxDynamicSharedMemorySize, SMEML);
    cudaFuncSetAttribute(mma_gemm_ln<2, 2, 256, 1024>, cudaFuncAttributeMaxDynamicSharedMemorySize, SMEML);

    // launch order puts QKV GEMM at launch #6 so ncu (-s 5 -c 1) profiles it
    // 1. LN1 stats
    ln_stats_kernel<<<TOK / 8, 256>>>(x, st1);
    // 2-5. weight transposes + fp16 rounding (tiny)
    transpose_kernel<<<dim3(768 / 32, 256 / 32),  dim3(32, 8)>>>(qkv_w,  wq, 256, 768);
    transpose_kernel<<<dim3(256 / 32, 256 / 32),  dim3(32, 8)>>>(proj_w, wp, 256, 256);
    transpose_kernel<<<dim3(1024 / 32, 256 / 32), dim3(32, 8)>>>(mlp_w1, w1, 256, 1024);
    transpose_kernel<<<dim3(256 / 32, 1024 / 32), dim3(32, 8)>>>(mlp_w2, w2, 1024, 256);
    // 6. QKV GEMM with fused LN1 + shift + window partition (half out)
    mma_gemm_ln<0, 1, 256, 768><<<dim3(768 / 128, TOK / 128), 256, SMEML>>>(
        x, wq, st1, ln1_g, ln1_b, qkv_b, qkvb);
    // 7. windowed attention (half in/out)
    attn_kernel<<<dim3(NWTOT, HEADS), 256>>>(qkvb, rel_bias, att);
    // 8. proj GEMM + window reverse + roll + residual (float out)
    mma_gemm<1, 256, 256><<<dim3(256 / 128, TOK / 128), 256, SMEM2>>>(att, wp, proj_b, x1, x);
    // 9. LN2 stats
    ln_stats_kernel<<<TOK / 8, 256>>>(x1, st2);
    // 10. MLP1 GEMM with fused LN2 + GELU epilogue (half out)
    mma_gemm_ln<2, 2, 256, 1024><<<dim3(1024 / 128, TOK / 128), 256, SMEML>>>(
        x1, w1, st2, ln2_g, ln2_b, mlp_b1, hbuf);
    // 11. MLP2 + residual -> d_out (float out)
    mma_gemm<3, 1024, 256><<<dim3(256 / 128, TOK / 128), 256, SMEM2>>>(hbuf, w2, mlp_b2, out, x1);
}